// round 8
// baseline (speedup 1.0000x reference)
#include <cuda_runtime.h>
#include <cuda_bf16.h>
#include <math.h>
#include <stdint.h>

// ---------------- problem constants ----------------
#define B_   32
#define NP_  192
#define NR_  72
#define NS_  36
#define FC_  64
#define M_   (B_*NP_)        // 6144
#define KFC_ (FC_*NS_)       // 2304
#define OUTW_ 78
#define PI_F 3.14159265358979323846f
#define NSPLIT 6

__device__ __forceinline__ int SIDX(int i) { return (i < 35) ? 2*i : 71; }

// ---------------- scratch offsets (floats) ----------------
#define O_F0T   0UL
#define O_F1T   8192000UL
#define O_F2T   10240000UL
#define O_AHI   10752000UL   // bf16 [6144][2304]
#define O_ALO   17829888UL
#define O_BHI   24907776UL   // bf16 [2304][64]
#define O_BLO   24981504UL
#define O_WQKV  25055232UL
#define O_F     25067520UL
#define O_QKV   25853952UL   // 6144*192
#define O_CPART 27033600UL   // 6 x 6144 x 64 fp32
#define O_ANCH  29392896UL
#define O_SXS   29411328UL
#define O_TT    29632512UL
#define O_SCALE 29634560UL
#define O_SHIFT 29636608UL
#define SCRATCH_FLOATS 29638656UL

__device__ float g_scratch[SCRATCH_FLOATS];

// ---------------- PTX helpers ----------------
__device__ __forceinline__ uint32_t smem_u32(const void* p) {
    uint32_t a;
    asm("{ .reg .u64 t; cvta.to.shared.u64 t, %1; cvt.u32.u64 %0, t; }" : "=r"(a) : "l"(p));
    return a;
}
__device__ __forceinline__ void ldsm4(uint32_t* r, uint32_t addr) {
    asm volatile("ldmatrix.sync.aligned.m8n8.x4.shared.b16 {%0,%1,%2,%3}, [%4];"
        : "=r"(r[0]), "=r"(r[1]), "=r"(r[2]), "=r"(r[3]) : "r"(addr));
}
__device__ __forceinline__ void ldsm4t(uint32_t* r, uint32_t addr) {
    asm volatile("ldmatrix.sync.aligned.m8n8.x4.trans.shared.b16 {%0,%1,%2,%3}, [%4];"
        : "=r"(r[0]), "=r"(r[1]), "=r"(r[2]), "=r"(r[3]) : "r"(addr));
}
__device__ __forceinline__ void mma16816(float* c, const uint32_t* a, const uint32_t* b) {
    asm volatile("mma.sync.aligned.m16n8k16.row.col.f32.bf16.bf16.f32 "
        "{%0,%1,%2,%3}, {%4,%5,%6,%7}, {%8,%9}, {%0,%1,%2,%3};"
        : "+f"(c[0]), "+f"(c[1]), "+f"(c[2]), "+f"(c[3])
        : "r"(a[0]), "r"(a[1]), "r"(a[2]), "r"(a[3]), "r"(b[0]), "r"(b[1]));
}
__device__ __forceinline__ void cpasync16(uint32_t dst, const void* src) {
    asm volatile("cp.async.cg.shared.global [%0], [%1], 16;" :: "r"(dst), "l"(src));
}
__device__ __forceinline__ void cpcommit() {
    asm volatile("cp.async.commit_group;" ::: "memory");
}
template<int N> __device__ __forceinline__ void cpwait() {
    asm volatile("cp.async.wait_group %0;" :: "n"(N) : "memory");
}

__device__ __forceinline__ float gelu_tanh(float x) {
    float x3 = x * x * x;
    return 0.5f * x * (1.0f + tanhf(0.7978845608028654f * (x + 0.044715f * x3)));
}
__device__ __forceinline__ float sigmoidf_(float x) { return 1.0f / (1.0f + expf(-x)); }

// ---------------- merged setup: pack_wb | pack_wqkv | init_anchor | time_mlp ----------------
__global__ void setup_misc_kernel(
    const float* __restrict__ Wfc,
    __nv_bfloat16* __restrict__ Bhi, __nv_bfloat16* __restrict__ Blo,
    const float* __restrict__ Wq, const float* __restrict__ Wk,
    const float* __restrict__ Wv, float* __restrict__ Wqkv,
    const float* __restrict__ inp, float* __restrict__ anchor, float* __restrict__ sxs,
    const int* __restrict__ tarr,
    const float* __restrict__ Wt1, const float* __restrict__ bt1,
    const float* __restrict__ Wt2, const float* __restrict__ bt2,
    const float* __restrict__ Wst, const float* __restrict__ bst,
    const float* __restrict__ Wtc, const float* __restrict__ btc,
    float* __restrict__ tt, float* __restrict__ scl, float* __restrict__ shf)
{
    __shared__ float se[64];
    __shared__ float h1[256];
    __shared__ float temb[256];
    __shared__ float tsil[256];
    int bx = blockIdx.x;
    int t = threadIdx.x;
    if (bx < 576) {
        int idx = bx * 256 + t;
        int k = idx >> 6, n = idx & 63;
        int c = k & 63, s = k >> 6;
        float v = Wfc[(c * 36 + s) * 64 + n];
        __nv_bfloat16 h = __float2bfloat16(v);
        __nv_bfloat16 l = __float2bfloat16(v - __bfloat162float(h));
        Bhi[idx] = h;
        Blo[idx] = l;
    } else if (bx < 624) {
        int idx = (bx - 576) * 256 + t;
        int k = idx / 192, n = idx % 192;
        float v;
        if (n < 64)        v = Wq[k * 64 + n];
        else if (n < 128)  v = Wk[k * 64 + (n - 64)];
        else               v = Wv[k * 64 + (n - 128)];
        Wqkv[idx] = v;
    } else if (bx < 648) {
        int bp = (bx - 624) * 256 + t;
        float sy = inp[bp * 3 + 0];
        float sx = inp[bp * 3 + 1];
        float th = inp[bp * 3 + 2];
        anchor[bp * 3 + 0] = sy;
        anchor[bp * 3 + 1] = sx;
        anchor[bp * 3 + 2] = th;
        float tan_t = tanf(th * PI_F);
        float ts = (fabsf(tan_t) < 0.001f) ? 0.001f : tan_t;
        float coef = 0.4f / ts;
        #pragma unroll
        for (int s = 0; s < NS_; s++) {
            int idx = SIDX(35 - s);
            sxs[bp * NS_ + s] = sx + ((float)idx * (1.0f / 71.0f) - sy) * coef;
        }
    } else {
        int b = bx - 648;
        float tv = (float)tarr[b];
        if (t < 64) {
            int i = (t < 32) ? t : t - 32;
            float factor = -logf(10000.0f) / 31.0f;
            float ang = tv * expf((float)i * factor);
            se[t] = (t < 32) ? sinf(ang) : cosf(ang);
        }
        __syncthreads();
        {
            float acc = bt1[t];
            #pragma unroll 8
            for (int k = 0; k < 64; k++) acc += se[k] * Wt1[k * 256 + t];
            h1[t] = gelu_tanh(acc);
        }
        __syncthreads();
        {
            float acc = bt2[t];
            for (int k = 0; k < 256; k++) acc += h1[k] * Wt2[k * 256 + t];
            temb[t] = acc;
            tsil[t] = acc * sigmoidf_(acc);
        }
        __syncthreads();
        if (t < 128) {
            float acc = bst[t];
            for (int k = 0; k < 256; k++) acc += tsil[k] * Wst[k * 128 + t];
            if (t < 64) scl[b * 64 + t] = acc;
            else        shf[b * 64 + (t - 64)] = acc;
        } else if (t < 192) {
            int m = t - 128;
            float acc = btc[m];
            for (int k = 0; k < 256; k++) acc += temb[k] * Wtc[k * 64 + m];
            tt[b * 64 + m] = acc;
        }
    }
}

// ---------------- transpose (B,C,HW)->(B,HW,C); two variants for launch-slot control ----------
__global__ void transpose_f0_kernel(const float* __restrict__ f0, float* __restrict__ o0)
{
    __shared__ float tile[32][33];
    int x0 = blockIdx.x * 32;
    int b  = blockIdx.z;
    int c0 = blockIdx.y * 32;
    int tx = threadIdx.x, ty = threadIdx.y;
    const int HW = 4000;
    const float* ib = f0 + (size_t)b * 64 * HW;
    float*       ob = o0 + (size_t)b * HW * 64;
    #pragma unroll
    for (int j = ty; j < 32; j += 8) {
        int x = x0 + tx;
        if (x < HW) tile[j][tx] = ib[(c0 + j) * HW + x];
    }
    __syncthreads();
    #pragma unroll
    for (int j = ty; j < 32; j += 8) {
        int x = x0 + j;
        if (x < HW) ob[(size_t)x * 64 + c0 + tx] = tile[tx][j];
    }
}
__global__ void transpose_f12_kernel(const float* __restrict__ f1, float* __restrict__ o1,
                                     const float* __restrict__ f2, float* __restrict__ o2)
{
    __shared__ float tile[32][33];
    int bx = blockIdx.x;
    const float* in; float* out; int HW; int x0;
    if (bx < 32) { in = f1; out = o1; HW = 1000; x0 = bx * 32; }
    else         { in = f2; out = o2; HW = 250;  x0 = (bx - 32) * 32; }
    int b  = blockIdx.z;
    int c0 = blockIdx.y * 32;
    int tx = threadIdx.x, ty = threadIdx.y;
    const float* ib = in  + (size_t)b * 64 * HW;
    float*       ob = out + (size_t)b * HW * 64;
    #pragma unroll
    for (int j = ty; j < 32; j += 8) {
        int x = x0 + tx;
        if (x < HW) tile[j][tx] = ib[(c0 + j) * HW + x];
    }
    __syncthreads();
    #pragma unroll
    for (int j = ty; j < 32; j += 8) {
        int x = x0 + j;
        if (x < HW) ob[(size_t)x * 64 + c0 + tx] = tile[tx][j];
    }
}

// ---------------- grid sample: warp handles GS_PPW points -> bf16 hi/lo row-major --------
#define GS_PPW 8
__global__ void gridsample_kernel(const float* __restrict__ featT, int H, int W,
                                  const float* __restrict__ sxs,
                                  __nv_bfloat16* __restrict__ Ahi, __nv_bfloat16* __restrict__ Alo)
{
    int warp = (blockIdx.x * 256 + threadIdx.x) >> 5;
    int lane = threadIdx.x & 31;
    #pragma unroll
    for (int p = 0; p < GS_PPW; p++) {
        int wi = warp * GS_PPW + p;
        if (wi >= M_ * NS_) return;
        int bp = wi / NS_;
        int s  = wi - bp * NS_;
        int b  = bp / NP_;
        float x = sxs[bp * NS_ + s] * (float)(W - 1);
        float y = ((float)SIDX(35 - s) * (1.0f / 71.0f)) * (float)(H - 1);
        float x0f = floorf(x), y0f = floorf(y);
        int x0 = (int)x0f, y0 = (int)y0f;
        float wx1 = x - x0f, wx0 = 1.0f - wx1;
        float wy1 = y - y0f, wy0 = 1.0f - wy1;
        const float* fb = featT + (size_t)b * H * W * 64;
        float ax = 0.0f, ay = 0.0f;
        int xs_[4] = {x0, x0 + 1, x0, x0 + 1};
        int ys_[4] = {y0, y0, y0 + 1, y0 + 1};
        float ws_[4] = {wx0 * wy0, wx1 * wy0, wx0 * wy1, wx1 * wy1};
        #pragma unroll
        for (int c = 0; c < 4; c++) {
            int xi = xs_[c], yi = ys_[c];
            if (xi >= 0 && xi < W && yi >= 0 && yi < H) {
                float2 v = *(const float2*)(fb + ((size_t)yi * W + xi) * 64 + lane * 2);
                ax += ws_[c] * v.x;
                ay += ws_[c] * v.y;
            }
        }
        size_t off = (size_t)bp * KFC_ + s * 64 + lane * 2;
        __nv_bfloat16 h0 = __float2bfloat16(ax);
        __nv_bfloat16 h1 = __float2bfloat16(ay);
        __nv_bfloat16 l0 = __float2bfloat16(ax - __bfloat162float(h0));
        __nv_bfloat16 l1 = __float2bfloat16(ay - __bfloat162float(h1));
        __nv_bfloat162 hv; hv.x = h0; hv.y = h1;
        __nv_bfloat162 lv; lv.x = l0; lv.y = l1;
        *(__nv_bfloat162*)(Ahi + off) = hv;
        *(__nv_bfloat162*)(Alo + off) = lv;
    }
}

// ---------------- fc GEMM via mma.sync bf16, 3-term split, split-K=6 ----------------
#define LDA_S 24
#define LDB_S 72
__global__ void __launch_bounds__(128, 3) fc_mma_kernel(
    const __nv_bfloat16* __restrict__ Ahi, const __nv_bfloat16* __restrict__ Alo,
    const __nv_bfloat16* __restrict__ Bhi, const __nv_bfloat16* __restrict__ Blo,
    float* __restrict__ Cparts)
{
    __shared__ __align__(16) __nv_bfloat16 sAh[2][128 * LDA_S];
    __shared__ __align__(16) __nv_bfloat16 sAl[2][128 * LDA_S];
    __shared__ __align__(16) __nv_bfloat16 sBh[2][16 * LDB_S];
    __shared__ __align__(16) __nv_bfloat16 sBl[2][16 * LDB_S];

    int row0 = blockIdx.x * 128;
    int sk = blockIdx.y;
    int kbase = sk * (KFC_ / NSPLIT);
    const int NSTEP = KFC_ / NSPLIT / 16;  // 24
    int t = threadIdx.x;
    int lane = t & 31, w = t >> 5;

    float acc[2][8][4];
    #pragma unroll
    for (int mt = 0; mt < 2; mt++)
        #pragma unroll
        for (int nb = 0; nb < 8; nb++)
            #pragma unroll
            for (int q = 0; q < 4; q++) acc[mt][nb][q] = 0.0f;

    auto copy_tile = [&](int step, int buf) {
        int kk = kbase + step * 16;
        #pragma unroll
        for (int j = 0; j < 2; j++) {
            int idx = j * 128 + t;
            int r = idx >> 1, h = (idx & 1) * 8;
            size_t gsrc = (size_t)(row0 + r) * KFC_ + kk + h;
            cpasync16(smem_u32(&sAh[buf][r * LDA_S + h]), Ahi + gsrc);
            cpasync16(smem_u32(&sAl[buf][r * LDA_S + h]), Alo + gsrc);
        }
        {
            int r = t >> 3, cc = (t & 7) * 8;
            size_t gsrc = (size_t)(kk + r) * 64 + cc;
            cpasync16(smem_u32(&sBh[buf][r * LDB_S + cc]), Bhi + gsrc);
            cpasync16(smem_u32(&sBl[buf][r * LDB_S + cc]), Blo + gsrc);
        }
    };

    copy_tile(0, 0); cpcommit();

    int arow_off = (w * 32 + (lane & 15)) * LDA_S + (lane >> 4) * 8;
    int brow_base = (lane & 15) * LDB_S + (lane >> 4) * 8;

    for (int s = 0; s < NSTEP; s++) {
        int buf = s & 1;
        if (s < NSTEP - 1) { copy_tile(s + 1, buf ^ 1); cpcommit(); cpwait<1>(); }
        else               { cpwait<0>(); }
        __syncthreads();

        uint32_t ah[2][4], al[2][4], bh[8][2], bl[8][2];
        ldsm4(ah[0], smem_u32(&sAh[buf][arow_off]));
        ldsm4(ah[1], smem_u32(&sAh[buf][arow_off + 16 * LDA_S]));
        ldsm4(al[0], smem_u32(&sAl[buf][arow_off]));
        ldsm4(al[1], smem_u32(&sAl[buf][arow_off + 16 * LDA_S]));
        #pragma unroll
        for (int nb16 = 0; nb16 < 4; nb16++) {
            uint32_t rr[4];
            ldsm4t(rr, smem_u32(&sBh[buf][brow_base + nb16 * 16]));
            bh[nb16 * 2][0] = rr[0]; bh[nb16 * 2][1] = rr[1];
            bh[nb16 * 2 + 1][0] = rr[2]; bh[nb16 * 2 + 1][1] = rr[3];
            ldsm4t(rr, smem_u32(&sBl[buf][brow_base + nb16 * 16]));
            bl[nb16 * 2][0] = rr[0]; bl[nb16 * 2][1] = rr[1];
            bl[nb16 * 2 + 1][0] = rr[2]; bl[nb16 * 2 + 1][1] = rr[3];
        }
        #pragma unroll
        for (int mt = 0; mt < 2; mt++)
            #pragma unroll
            for (int nb = 0; nb < 8; nb++) {
                mma16816(acc[mt][nb], ah[mt], bh[nb]);
                mma16816(acc[mt][nb], ah[mt], bl[nb]);
                mma16816(acc[mt][nb], al[mt], bh[nb]);
            }
        __syncthreads();
    }

    float* Cp = Cparts + (size_t)sk * M_ * 64;
    #pragma unroll
    for (int mt = 0; mt < 2; mt++) {
        int r = row0 + w * 32 + mt * 16 + (lane >> 2);
        #pragma unroll
        for (int nb = 0; nb < 8; nb++) {
            int c = nb * 8 + (lane & 3) * 2;
            float2 v0; v0.x = acc[mt][nb][0]; v0.y = acc[mt][nb][1];
            float2 v1; v1.x = acc[mt][nb][2]; v1.y = acc[mt][nb][3];
            *(float2*)&Cp[(size_t)r * 64 + c] = v0;
            *(float2*)&Cp[(size_t)(r + 8) * 64 + c] = v1;
        }
    }
}

// ---------------- qkvF: combine split-K + bias/relu/tt -> F ; QKV = F @ Wqkv ----------------
#define QKVF_SMEM_FLOATS (4352 + 64 * 196)
__global__ void __launch_bounds__(256, 1) qkvF_kernel(
    const float* __restrict__ Cparts, const float* __restrict__ bias,
    const float* __restrict__ tt, const float* __restrict__ Wqkv,
    float* __restrict__ F, float* __restrict__ QKV)
{
    extern __shared__ float sm[];
    float* Ftr = sm;          // [64][68] : Ftr[k][m]
    float* Ws  = sm + 4352;   // [64][196]

    int row0 = blockIdx.x * 64;
    int b = row0 / NP_;
    int t = threadIdx.x;
    int tx = t & 15, ty = t >> 4;

    #pragma unroll
    for (int g = 0; g < 4; g++) {
        int idx = g * 256 + t;
        int m = idx >> 4;
        int n4 = (idx & 15) * 4;
        size_t off = (size_t)(row0 + m) * 64 + n4;
        float4 p = *(const float4*)(Cparts + off);
        #pragma unroll
        for (int sk = 1; sk < NSPLIT; sk++) {
            float4 q = *(const float4*)(Cparts + off + (size_t)sk * M_ * 64);
            p.x += q.x; p.y += q.y; p.z += q.z; p.w += q.w;
        }
        float4 bs = *(const float4*)(bias + n4);
        float4 tv = *(const float4*)(tt + b * 64 + n4);
        float4 o;
        o.x = fmaxf(p.x + bs.x, 0.0f) + tv.x;
        o.y = fmaxf(p.y + bs.y, 0.0f) + tv.y;
        o.z = fmaxf(p.z + bs.z, 0.0f) + tv.z;
        o.w = fmaxf(p.w + bs.w, 0.0f) + tv.w;
        *(float4*)(F + off) = o;
        Ftr[(n4 + 0) * 68 + m] = o.x;
        Ftr[(n4 + 1) * 68 + m] = o.y;
        Ftr[(n4 + 2) * 68 + m] = o.z;
        Ftr[(n4 + 3) * 68 + m] = o.w;
    }
    for (int idx = t; idx < 64 * 192; idx += 256) {
        int k = idx / 192, n = idx - k * 192;
        Ws[k * 196 + n] = Wqkv[idx];
    }
    __syncthreads();

    float acc[4][12];
    #pragma unroll
    for (int i = 0; i < 4; i++)
        #pragma unroll
        for (int j = 0; j < 12; j++) acc[i][j] = 0.0f;
    for (int k = 0; k < 64; k++) {
        float4 a4 = *(const float4*)&Ftr[k * 68 + ty * 4];
        float a[4] = {a4.x, a4.y, a4.z, a4.w};
        float4 b0 = *(const float4*)&Ws[k * 196 + tx * 12];
        float4 b1 = *(const float4*)&Ws[k * 196 + tx * 12 + 4];
        float4 b2 = *(const float4*)&Ws[k * 196 + tx * 12 + 8];
        float bb[12] = {b0.x,b0.y,b0.z,b0.w, b1.x,b1.y,b1.z,b1.w, b2.x,b2.y,b2.z,b2.w};
        #pragma unroll
        for (int i = 0; i < 4; i++)
            #pragma unroll
            for (int j = 0; j < 12; j++) acc[i][j] += a[i] * bb[j];
    }
    #pragma unroll
    for (int i = 0; i < 4; i++) {
        int m = row0 + ty * 4 + i;
        #pragma unroll
        for (int j = 0; j < 12; j++)
            QKV[(size_t)m * 192 + tx * 12 + j] = acc[i][j];
    }
}

// ---------------- fused attention + tail (heads + anchor update + output) ----------------
// layout (floats): QT 0 [64][68]; KT 4352 [64][196] (later P); Vs 16896 [192][68];
// red 29952 [64][16]; red2 30976; F2s 32000 [64][68]; T1 36352; T2 40704;
// Wb 45056 [64][80]; RG 50176 [64][76]; total 55040 floats = 220160 B
#define ATTAIL_SMEM_FLOATS 55040
__global__ void __launch_bounds__(256, 1) attn_tail_kernel(
    const float* __restrict__ QKV, const float* __restrict__ Wo,
    const float* __restrict__ F, const float* __restrict__ scl, const float* __restrict__ shf,
    const float* __restrict__ Wc1, const float* __restrict__ bc1,
    const float* __restrict__ Wc2, const float* __restrict__ bc2,
    const float* __restrict__ Wcls, const float* __restrict__ bcls,
    const float* __restrict__ Wr1, const float* __restrict__ br1,
    const float* __restrict__ Wr2, const float* __restrict__ br2,
    const float* __restrict__ Wreg, const float* __restrict__ breg,
    float* __restrict__ anchor, float* __restrict__ sxs, float* __restrict__ out)
{
    extern __shared__ float sm[];
    float* QT  = sm;
    float* KT  = sm + 4352;
    float* Vs  = sm + 16896;
    float* red = sm + 29952;
    float* red2= sm + 30976;
    float* F2s = sm + 32000;
    float* T1  = sm + 36352;
    float* T2  = sm + 40704;
    float* Wb  = sm + 45056;
    float* RG  = sm + 50176;

    int bid = blockIdx.x;
    int b = bid / 3;
    int row0 = (bid % 3) * 64;
    int t = threadIdx.x;
    int tx = t & 15, ty = t >> 4;
    const float* qkvb = QKV + (size_t)b * NP_ * 192;

    for (int idx = t; idx < 4096; idx += 256) {
        int r = idx >> 6, d = idx & 63;
        QT[d * 68 + r] = qkvb[(size_t)(row0 + r) * 192 + d];
    }
    for (int idx = t; idx < 12288; idx += 256) {
        int n = idx >> 6, d = idx & 63;
        KT[d * 196 + n] = qkvb[(size_t)n * 192 + 64 + d];
    }
    for (int idx = t; idx < 12288; idx += 256) {
        int k = idx >> 6, n = idx & 63;
        Vs[k * 68 + n] = qkvb[(size_t)k * 192 + 128 + n];
    }
    __syncthreads();

    // scores
    float acc[4][12];
    #pragma unroll
    for (int i = 0; i < 4; i++)
        #pragma unroll
        for (int j = 0; j < 12; j++) acc[i][j] = 0.0f;
    for (int d = 0; d < 64; d++) {
        float4 a4 = *(const float4*)&QT[d * 68 + ty * 4];
        float a[4] = {a4.x, a4.y, a4.z, a4.w};
        float4 b0 = *(const float4*)&KT[d * 196 + tx * 12];
        float4 b1 = *(const float4*)&KT[d * 196 + tx * 12 + 4];
        float4 b2 = *(const float4*)&KT[d * 196 + tx * 12 + 8];
        float bb[12] = {b0.x,b0.y,b0.z,b0.w, b1.x,b1.y,b1.z,b1.w, b2.x,b2.y,b2.z,b2.w};
        #pragma unroll
        for (int i = 0; i < 4; i++)
            #pragma unroll
            for (int j = 0; j < 12; j++) acc[i][j] += a[i] * bb[j];
    }
    #pragma unroll
    for (int i = 0; i < 4; i++) {
        float m = -1e30f;
        #pragma unroll
        for (int j = 0; j < 12; j++) { acc[i][j] *= 0.125f; m = fmaxf(m, acc[i][j]); }
        red[(ty * 4 + i) * 16 + tx] = m;
    }
    __syncthreads();
    float inv_[4];
    #pragma unroll
    for (int i = 0; i < 4; i++) {
        int r = ty * 4 + i;
        float rm = red[r * 16];
        #pragma unroll
        for (int x = 1; x < 16; x++) rm = fmaxf(rm, red[r * 16 + x]);
        float s = 0.0f;
        #pragma unroll
        for (int j = 0; j < 12; j++) { acc[i][j] = expf(acc[i][j] - rm); s += acc[i][j]; }
        red2[r * 16 + tx] = s;
    }
    __syncthreads();
    #pragma unroll
    for (int i = 0; i < 4; i++) {
        int r = ty * 4 + i;
        float rs = red2[r * 16];
        #pragma unroll
        for (int x = 1; x < 16; x++) rs += red2[r * 16 + x];
        inv_[i] = 1.0f / rs;
    }
    #pragma unroll
    for (int i = 0; i < 4; i++)
        #pragma unroll
        for (int j = 0; j < 12; j++)
            KT[(ty * 4 + i) * 196 + tx * 12 + j] = acc[i][j] * inv_[i];
    __syncthreads();

    // P @ V
    float acc2[4][4];
    #pragma unroll
    for (int i = 0; i < 4; i++)
        #pragma unroll
        for (int j = 0; j < 4; j++) acc2[i][j] = 0.0f;
    for (int k = 0; k < 192; k++) {
        float4 b4 = *(const float4*)&Vs[k * 68 + tx * 4];
        #pragma unroll
        for (int i = 0; i < 4; i++) {
            float a = KT[(ty * 4 + i) * 196 + k];
            acc2[i][0] += a * b4.x; acc2[i][1] += a * b4.y;
            acc2[i][2] += a * b4.z; acc2[i][3] += a * b4.w;
        }
    }
    __syncthreads();
    #pragma unroll
    for (int i = 0; i < 4; i++)
        #pragma unroll
        for (int j = 0; j < 4; j++)
            QT[(ty * 4 + i) * 68 + tx * 4 + j] = acc2[i][j];
    for (int idx = t; idx < 4096; idx += 256) {
        int k = idx >> 6, n = idx & 63;
        Vs[k * 68 + n] = Wo[idx];
    }
    __syncthreads();

    // O @ Wo + residual + FiLM -> F2s (smem)
    float acc3[4][4];
    #pragma unroll
    for (int i = 0; i < 4; i++)
        #pragma unroll
        for (int j = 0; j < 4; j++) acc3[i][j] = 0.0f;
    for (int k = 0; k < 64; k++) {
        float4 b4 = *(const float4*)&Vs[k * 68 + tx * 4];
        #pragma unroll
        for (int i = 0; i < 4; i++) {
            float a = QT[(ty * 4 + i) * 68 + k];
            acc3[i][0] += a * b4.x; acc3[i][1] += a * b4.y;
            acc3[i][2] += a * b4.z; acc3[i][3] += a * b4.w;
        }
    }
    #pragma unroll
    for (int i = 0; i < 4; i++) {
        int tok = b * NP_ + row0 + ty * 4 + i;
        #pragma unroll
        for (int j = 0; j < 4; j++) {
            int n = tx * 4 + j;
            float v = acc3[i][j] + F[(size_t)tok * 64 + n];
            v = v * (scl[b * 64 + n] + 1.0f) + shf[b * 64 + n];
            F2s[(ty * 4 + i) * 68 + n] = v;
        }
    }
    // stage Wc1 while F2s settles
    for (int idx = t; idx < 4096; idx += 256)
        Wb[(idx >> 6) * 68 + (idx & 63)] = Wc1[idx];
    __syncthreads();

    // 64-row head GEMM helper: OUT = relu(IN @ Wb + bias)
#define MMH(IN, OUT, BIAS)                                                     \
    {                                                                          \
        float ac[4][4];                                                        \
        _Pragma("unroll")                                                      \
        for (int i = 0; i < 4; i++)                                            \
            { ac[i][0]=0; ac[i][1]=0; ac[i][2]=0; ac[i][3]=0; }                \
        for (int k = 0; k < 64; k++) {                                         \
            float4 b4 = *(const float4*)&Wb[k * 68 + tx * 4];                  \
            _Pragma("unroll")                                                  \
            for (int i = 0; i < 4; i++) {                                      \
                float a = IN[(ty * 4 + i) * 68 + k];                           \
                ac[i][0]+=a*b4.x; ac[i][1]+=a*b4.y;                            \
                ac[i][2]+=a*b4.z; ac[i][3]+=a*b4.w;                            \
            }                                                                  \
        }                                                                      \
        _Pragma("unroll")                                                      \
        for (int i = 0; i < 4; i++)                                            \
            _Pragma("unroll")                                                  \
            for (int j = 0; j < 4; j++) {                                      \
                int n = tx * 4 + j;                                            \
                OUT[(ty * 4 + i) * 68 + n] = fmaxf(ac[i][j] + BIAS[n], 0.0f);  \
            }                                                                  \
    }

    MMH(F2s, T1, bc1);
    __syncthreads();
    for (int idx = t; idx < 4096; idx += 256)
        Wb[(idx >> 6) * 68 + (idx & 63)] = Wc2[idx];
    __syncthreads();
    MMH(T1, T2, bc2);
    __syncthreads();
    // cls head (N=2) -> out; stage Wr1 in parallel
    if (t < 128) {
        int r = t >> 1, c = t & 1;
        float s = bcls[c];
        #pragma unroll 8
        for (int k = 0; k < 64; k++) s += T2[r * 68 + k] * Wcls[k * 2 + c];
        out[(size_t)(b * NP_ + row0 + r) * OUTW_ + c] = s;
    }
    for (int idx = t; idx < 4096; idx += 256)
        Wb[(idx >> 6) * 68 + (idx & 63)] = Wr1[idx];
    __syncthreads();
    MMH(F2s, T1, br1);
    __syncthreads();
    for (int idx = t; idx < 4096; idx += 256)
        Wb[(idx >> 6) * 68 + (idx & 63)] = Wr2[idx];
    __syncthreads();
    MMH(T1, T2, br2);
    __syncthreads();
    for (int idx = t; idx < 64 * 76; idx += 256) Wb[idx] = Wreg[idx];
    __syncthreads();
    for (int idx = t; idx < 64 * 76; idx += 256) {
        int r = idx / 76, n = idx - r * 76;
        float s = breg[n];
        #pragma unroll 8
        for (int k = 0; k < 64; k++) s += T2[r * 68 + k] * Wb[k * 76 + n];
        RG[idx] = s;
    }
    __syncthreads();

    if (t < 64) {
        int bp = b * NP_ + row0 + t;
        const float* rg = &RG[t * 76];
        float sy = anchor[bp * 3 + 0] + rg[0];
        float sx = anchor[bp * 3 + 1] + rg[1];
        float th = anchor[bp * 3 + 2] + rg[2];
        anchor[bp * 3 + 0] = sy;
        anchor[bp * 3 + 1] = sx;
        anchor[bp * 3 + 2] = th;
        float tan_t = tanf(th * PI_F);
        float ts = (fabsf(tan_t) < 0.001f) ? 0.001f : tan_t;
        float coef = 0.4f / ts;
        float* o = out + (size_t)bp * OUTW_;
        o[2] = sy; o[3] = sx; o[4] = th;
        o[5] = rg[3];
        #pragma unroll 8
        for (int r = 0; r < NR_; r++) {
            float xr = sx + ((float)r * (1.0f / 71.0f) - sy) * coef;
            o[6 + r] = xr + rg[4 + r];
        }
        #pragma unroll
        for (int s = 0; s < NS_; s++) {
            int idx = SIDX(35 - s);
            sxs[bp * NS_ + s] = sx + ((float)idx * (1.0f / 71.0f) - sy) * coef;
        }
    }
#undef MMH
}

// ---------------- host ----------------
extern "C" void kernel_launch(void* const* d_in, const int* in_sizes, int n_in,
                              void* d_out, int out_size)
{
    const float *feat0 = nullptr, *feat1 = nullptr, *feat2 = nullptr, *inputs = nullptr;
    const int* tarr = nullptr;
    const float *W_t1 = nullptr, *b_t1 = nullptr, *W_t2 = nullptr, *b_t2 = nullptr;
    const float *W_st = nullptr, *b_st = nullptr, *W_tc = nullptr, *b_tc = nullptr;
    const float *W_fc = nullptr, *b_fc = nullptr;
    const float *W_q = nullptr, *W_k = nullptr, *W_v = nullptr, *W_o = nullptr;
    const float *W_c1 = nullptr, *b_c1 = nullptr, *W_c2 = nullptr, *b_c2 = nullptr;
    const float *W_r1 = nullptr, *b_r1 = nullptr, *W_r2 = nullptr, *b_r2 = nullptr;
    const float *W_cls = nullptr, *b_cls = nullptr, *W_reg = nullptr, *b_reg = nullptr;

    int idx16384 = 0, idx4096 = 0, idx256 = 0, idx64 = 0;
    int idxWst = -1;
    int idx128_pos[2] = {-1, -1}; int n128 = 0;
    const float* p4096[8] = {0};
    const float* p64[6] = {0};

    for (int i = 0; i < n_in; i++) {
        const float* p = (const float*)d_in[i];
        switch (in_sizes[i]) {
            case 8192000: feat0 = p; break;
            case 2048000: feat1 = p; break;
            case 512000:  feat2 = p; break;
            case 18432:   inputs = p; break;
            case 32:      tarr = (const int*)d_in[i]; break;
            case 65536:   W_t2 = p; break;
            case 32768:   W_st = p; idxWst = i; break;
            case 147456:  W_fc = p; break;
            case 4864:    W_reg = p; break;
            case 2:       b_cls = p; break;
            case 76:      b_reg = p; break;
            case 16384:   if (idx16384++ == 0) W_t1 = p; else W_tc = p; break;
            case 4096:    if (idx4096 < 8) p4096[idx4096++] = p; break;
            case 256:     if (idx256++ == 0) b_t1 = p; else b_t2 = p; break;
            case 64:      if (idx64 < 6) p64[idx64++] = p; break;
            case 128:     if (n128 < 2) idx128_pos[n128++] = i; break;
            default: break;
        }
    }
    W_q = p4096[0]; W_k = p4096[1]; W_v = p4096[2]; W_o = p4096[3];
    W_c1 = p4096[4]; W_c2 = p4096[5]; W_r1 = p4096[6]; W_r2 = p4096[7];
    b_tc = p64[0]; b_fc = p64[1]; b_c1 = p64[2]; b_c2 = p64[3]; b_r1 = p64[4]; b_r2 = p64[5];
    if (n128 == 2) {
        if (idx128_pos[0] == idxWst + 1) {
            b_st  = (const float*)d_in[idx128_pos[0]];
            W_cls = (const float*)d_in[idx128_pos[1]];
        } else if (idx128_pos[1] == idxWst + 1) {
            b_st  = (const float*)d_in[idx128_pos[1]];
            W_cls = (const float*)d_in[idx128_pos[0]];
        } else {
            W_cls = (const float*)d_in[idx128_pos[0]];
            b_st  = (const float*)d_in[idx128_pos[1]];
        }
    }

    static int attr_done = 0;
    if (!attr_done) {
        cudaFuncSetAttribute(attn_tail_kernel, cudaFuncAttributeMaxDynamicSharedMemorySize,
                             ATTAIL_SMEM_FLOATS * 4);
        cudaFuncSetAttribute(qkvF_kernel, cudaFuncAttributeMaxDynamicSharedMemorySize,
                             QKVF_SMEM_FLOATS * 4);
        attr_done = 1;
    }

    float* S;
    cudaGetSymbolAddress((void**)&S, g_scratch);
    float* f0T = S + O_F0T;  float* f1T = S + O_F1T;  float* f2T = S + O_F2T;
    __nv_bfloat16* gAhi = (__nv_bfloat16*)(S + O_AHI);
    __nv_bfloat16* gAlo = (__nv_bfloat16*)(S + O_ALO);
    __nv_bfloat16* gBhi = (__nv_bfloat16*)(S + O_BHI);
    __nv_bfloat16* gBlo = (__nv_bfloat16*)(S + O_BLO);
    float* Wqkv = S + O_WQKV;
    float* gF = S + O_F; float* gQKV = S + O_QKV;
    float* gCP = S + O_CPART;
    float* gANCH = S + O_ANCH; float* gSXS = S + O_SXS;
    float* gTT = S + O_TT; float* gSCL = S + O_SCALE; float* gSHF = S + O_SHIFT;
    float* outP = (float*)d_out;

    const float* feats[3] = { f2T, f1T, f0T };
    const int Hs[3] = { 10, 20, 40 };
    const int Ws_[3] = { 25, 50, 100 };
    int gsBlocks = (M_ * NS_ + GS_PPW * 8 - 1) / (GS_PPW * 8);

    // launch order: our #4 is the ncu-profiled launch -> gridsample this round
    setup_misc_kernel<<<680, 256>>>(W_fc, gBhi, gBlo, W_q, W_k, W_v, Wqkv,
                                    inputs, gANCH, gSXS,
                                    tarr, W_t1, b_t1, W_t2, b_t2, W_st, b_st,
                                    W_tc, b_tc, gTT, gSCL, gSHF);                     // 1
    transpose_f0_kernel<<<dim3(125, 2, B_), dim3(32, 8)>>>(feat0, f0T);               // 2
    transpose_f12_kernel<<<dim3(40, 2, B_), dim3(32, 8)>>>(feat1, f1T, feat2, f2T);   // 3
    gridsample_kernel<<<gsBlocks, 256>>>(feats[0], Hs[0], Ws_[0], gSXS, gAhi, gAlo);  // 4 [prof]
    fc_mma_kernel<<<dim3(48, NSPLIT), 128>>>(gAhi, gAlo, gBhi, gBlo, gCP);            // 5

    for (int it = 0; it < 3; it++) {
        if (it > 0) {
            gridsample_kernel<<<gsBlocks, 256>>>(feats[it], Hs[it], Ws_[it], gSXS, gAhi, gAlo);
            fc_mma_kernel<<<dim3(48, NSPLIT), 128>>>(gAhi, gAlo, gBhi, gBlo, gCP);
        }
        qkvF_kernel<<<M_ / 64, 256, QKVF_SMEM_FLOATS * 4>>>(gCP, b_fc, gTT, Wqkv, gF, gQKV);
        attn_tail_kernel<<<B_ * 3, 256, ATTAIL_SMEM_FLOATS * 4>>>(
            gQKV, W_o, gF, gSCL, gSHF,
            W_c1, b_c1, W_c2, b_c2, W_cls, b_cls, W_r1, b_r1, W_r2, b_r2,
            W_reg, b_reg, gANCH, gSXS, outP);
    }
    (void)out_size; (void)n_in;
}

// round 9
// speedup vs baseline: 1.0508x; 1.0508x over previous
#include <cuda_runtime.h>
#include <cuda_bf16.h>
#include <math.h>
#include <stdint.h>

// ---------------- problem constants ----------------
#define B_   32
#define NP_  192
#define NR_  72
#define NS_  36
#define FC_  64
#define M_   (B_*NP_)        // 6144
#define KFC_ (FC_*NS_)       // 2304
#define OUTW_ 78
#define PI_F 3.14159265358979323846f
#define NSPLIT 6

__device__ __forceinline__ int SIDX(int i) { return (i < 35) ? 2*i : 71; }

// ---------------- scratch offsets (floats) ----------------
#define O_F0T   0UL
#define O_F1T   8192000UL
#define O_F2T   10240000UL
#define O_AHI   10752000UL   // bf16 [6144][2304]
#define O_ALO   17829888UL
#define O_BHI   24907776UL   // bf16 [2304][64]
#define O_BLO   24981504UL
#define O_WQKV  25055232UL
#define O_F     25067520UL
#define O_F2    25460736UL
#define O_QKV   25853952UL   // 6144*192
#define O_CPART 27033600UL   // 6 x 6144 x 64 fp32
#define O_ANCH  29392896UL
#define O_SXS   29411328UL
#define O_TT    29632512UL
#define O_SCALE 29634560UL
#define O_SHIFT 29636608UL
#define SCRATCH_FLOATS 29638656UL

__device__ float g_scratch[SCRATCH_FLOATS];

// ---------------- PTX helpers ----------------
__device__ __forceinline__ uint32_t smem_u32(const void* p) {
    uint32_t a;
    asm("{ .reg .u64 t; cvta.to.shared.u64 t, %1; cvt.u32.u64 %0, t; }" : "=r"(a) : "l"(p));
    return a;
}
__device__ __forceinline__ void ldsm4(uint32_t* r, uint32_t addr) {
    asm volatile("ldmatrix.sync.aligned.m8n8.x4.shared.b16 {%0,%1,%2,%3}, [%4];"
        : "=r"(r[0]), "=r"(r[1]), "=r"(r[2]), "=r"(r[3]) : "r"(addr));
}
__device__ __forceinline__ void ldsm4t(uint32_t* r, uint32_t addr) {
    asm volatile("ldmatrix.sync.aligned.m8n8.x4.trans.shared.b16 {%0,%1,%2,%3}, [%4];"
        : "=r"(r[0]), "=r"(r[1]), "=r"(r[2]), "=r"(r[3]) : "r"(addr));
}
__device__ __forceinline__ void mma16816(float* c, const uint32_t* a, const uint32_t* b) {
    asm volatile("mma.sync.aligned.m16n8k16.row.col.f32.bf16.bf16.f32 "
        "{%0,%1,%2,%3}, {%4,%5,%6,%7}, {%8,%9}, {%0,%1,%2,%3};"
        : "+f"(c[0]), "+f"(c[1]), "+f"(c[2]), "+f"(c[3])
        : "r"(a[0]), "r"(a[1]), "r"(a[2]), "r"(a[3]), "r"(b[0]), "r"(b[1]));
}
__device__ __forceinline__ void cpasync16(uint32_t dst, const void* src) {
    asm volatile("cp.async.cg.shared.global [%0], [%1], 16;" :: "r"(dst), "l"(src));
}
__device__ __forceinline__ void cpcommit() {
    asm volatile("cp.async.commit_group;" ::: "memory");
}
template<int N> __device__ __forceinline__ void cpwait() {
    asm volatile("cp.async.wait_group %0;" :: "n"(N) : "memory");
}

__device__ __forceinline__ float gelu_tanh(float x) {
    float x3 = x * x * x;
    return 0.5f * x * (1.0f + tanhf(0.7978845608028654f * (x + 0.044715f * x3)));
}
__device__ __forceinline__ float sigmoidf_(float x) { return 1.0f / (1.0f + expf(-x)); }

// ---------------- merged setup: pack_wb | pack_wqkv | init_anchor | time_mlp ----------------
__global__ void setup_misc_kernel(
    const float* __restrict__ Wfc,
    __nv_bfloat16* __restrict__ Bhi, __nv_bfloat16* __restrict__ Blo,
    const float* __restrict__ Wq, const float* __restrict__ Wk,
    const float* __restrict__ Wv, float* __restrict__ Wqkv,
    const float* __restrict__ inp, float* __restrict__ anchor, float* __restrict__ sxs,
    const int* __restrict__ tarr,
    const float* __restrict__ Wt1, const float* __restrict__ bt1,
    const float* __restrict__ Wt2, const float* __restrict__ bt2,
    const float* __restrict__ Wst, const float* __restrict__ bst,
    const float* __restrict__ Wtc, const float* __restrict__ btc,
    float* __restrict__ tt, float* __restrict__ scl, float* __restrict__ shf)
{
    __shared__ float se[64];
    __shared__ float h1[256];
    __shared__ float temb[256];
    __shared__ float tsil[256];
    int bx = blockIdx.x;
    int t = threadIdx.x;
    if (bx < 576) {
        int idx = bx * 256 + t;
        int k = idx >> 6, n = idx & 63;
        int c = k & 63, s = k >> 6;
        float v = Wfc[(c * 36 + s) * 64 + n];
        __nv_bfloat16 h = __float2bfloat16(v);
        __nv_bfloat16 l = __float2bfloat16(v - __bfloat162float(h));
        Bhi[idx] = h;
        Blo[idx] = l;
    } else if (bx < 624) {
        int idx = (bx - 576) * 256 + t;
        int k = idx / 192, n = idx % 192;
        float v;
        if (n < 64)        v = Wq[k * 64 + n];
        else if (n < 128)  v = Wk[k * 64 + (n - 64)];
        else               v = Wv[k * 64 + (n - 128)];
        Wqkv[idx] = v;
    } else if (bx < 648) {
        int bp = (bx - 624) * 256 + t;
        float sy = inp[bp * 3 + 0];
        float sx = inp[bp * 3 + 1];
        float th = inp[bp * 3 + 2];
        anchor[bp * 3 + 0] = sy;
        anchor[bp * 3 + 1] = sx;
        anchor[bp * 3 + 2] = th;
        float tan_t = tanf(th * PI_F);
        float ts = (fabsf(tan_t) < 0.001f) ? 0.001f : tan_t;
        float coef = 0.4f / ts;
        #pragma unroll
        for (int s = 0; s < NS_; s++) {
            int idx = SIDX(35 - s);
            sxs[bp * NS_ + s] = sx + ((float)idx * (1.0f / 71.0f) - sy) * coef;
        }
    } else {
        int b = bx - 648;
        float tv = (float)tarr[b];
        if (t < 64) {
            int i = (t < 32) ? t : t - 32;
            float factor = -logf(10000.0f) / 31.0f;
            float ang = tv * expf((float)i * factor);
            se[t] = (t < 32) ? sinf(ang) : cosf(ang);
        }
        __syncthreads();
        {
            float acc = bt1[t];
            #pragma unroll 8
            for (int k = 0; k < 64; k++) acc += se[k] * Wt1[k * 256 + t];
            h1[t] = gelu_tanh(acc);
        }
        __syncthreads();
        {
            float acc = bt2[t];
            for (int k = 0; k < 256; k++) acc += h1[k] * Wt2[k * 256 + t];
            temb[t] = acc;
            tsil[t] = acc * sigmoidf_(acc);
        }
        __syncthreads();
        if (t < 128) {
            float acc = bst[t];
            for (int k = 0; k < 256; k++) acc += tsil[k] * Wst[k * 128 + t];
            if (t < 64) scl[b * 64 + t] = acc;
            else        shf[b * 64 + (t - 64)] = acc;
        } else if (t < 192) {
            int m = t - 128;
            float acc = btc[m];
            for (int k = 0; k < 256; k++) acc += temb[k] * Wtc[k * 64 + m];
            tt[b * 64 + m] = acc;
        }
    }
}

// ---------------- transpose (B,C,HW)->(B,HW,C) ----------------
__global__ void transpose_f0_kernel(const float* __restrict__ f0, float* __restrict__ o0)
{
    __shared__ float tile[32][33];
    int x0 = blockIdx.x * 32;
    int b  = blockIdx.z;
    int c0 = blockIdx.y * 32;
    int tx = threadIdx.x, ty = threadIdx.y;
    const int HW = 4000;
    const float* ib = f0 + (size_t)b * 64 * HW;
    float*       ob = o0 + (size_t)b * HW * 64;
    #pragma unroll
    for (int j = ty; j < 32; j += 8) {
        int x = x0 + tx;
        if (x < HW) tile[j][tx] = ib[(c0 + j) * HW + x];
    }
    __syncthreads();
    #pragma unroll
    for (int j = ty; j < 32; j += 8) {
        int x = x0 + j;
        if (x < HW) ob[(size_t)x * 64 + c0 + tx] = tile[tx][j];
    }
}
__global__ void transpose_f12_kernel(const float* __restrict__ f1, float* __restrict__ o1,
                                     const float* __restrict__ f2, float* __restrict__ o2)
{
    __shared__ float tile[32][33];
    int bx = blockIdx.x;
    const float* in; float* out; int HW; int x0;
    if (bx < 32) { in = f1; out = o1; HW = 1000; x0 = bx * 32; }
    else         { in = f2; out = o2; HW = 250;  x0 = (bx - 32) * 32; }
    int b  = blockIdx.z;
    int c0 = blockIdx.y * 32;
    int tx = threadIdx.x, ty = threadIdx.y;
    const float* ib = in  + (size_t)b * 64 * HW;
    float*       ob = out + (size_t)b * HW * 64;
    #pragma unroll
    for (int j = ty; j < 32; j += 8) {
        int x = x0 + tx;
        if (x < HW) tile[j][tx] = ib[(c0 + j) * HW + x];
    }
    __syncthreads();
    #pragma unroll
    for (int j = ty; j < 32; j += 8) {
        int x = x0 + j;
        if (x < HW) ob[(size_t)x * 64 + c0 + tx] = tile[tx][j];
    }
}

// ---------------- grid sample: lane-parallel scalars + shfl broadcast ----------------
// warp handles 32 points: lane L owns scalar setup for point base+L; loop j broadcasts
// lane j's (4 clamped corner offsets, 4 validity-folded weights, output offset) and all
// lanes gather their 2 channels.
__global__ void gridsample_kernel(const float* __restrict__ featT, int H, int W,
                                  const float* __restrict__ sxs,
                                  __nv_bfloat16* __restrict__ Ahi, __nv_bfloat16* __restrict__ Alo)
{
    int warp = (blockIdx.x * 256 + threadIdx.x) >> 5;
    int lane = threadIdx.x & 31;
    int base = warp * 32;
    if (base >= M_ * NS_) return;

    int wi = base + lane;
    if (wi >= M_ * NS_) wi = M_ * NS_ - 1;
    int bp = wi / NS_;
    int s  = wi - bp * NS_;
    int b  = bp / NP_;
    float x = sxs[bp * NS_ + s] * (float)(W - 1);
    float y = ((float)SIDX(35 - s) * (1.0f / 71.0f)) * (float)(H - 1);
    float x0f = floorf(x), y0f = floorf(y);
    int x0 = (int)x0f, y0 = (int)y0f;
    float wx1 = x - x0f, wx0 = 1.0f - wx1;
    float wy1 = y - y0f, wy0 = 1.0f - wy1;
    int x1 = x0 + 1, y1 = y0 + 1;
    float vx0 = (x0 >= 0 && x0 < W) ? 1.0f : 0.0f;
    float vx1 = (x1 >= 0 && x1 < W) ? 1.0f : 0.0f;
    float vy0 = (y0 >= 0 && y0 < H) ? 1.0f : 0.0f;
    float vy1 = (y1 >= 0 && y1 < H) ? 1.0f : 0.0f;
    int x0c = min(max(x0, 0), W - 1), x1c = min(max(x1, 0), W - 1);
    int y0c = min(max(y0, 0), H - 1), y1c = min(max(y1, 0), H - 1);
    float w00 = wx0 * wy0 * vx0 * vy0;
    float w01 = wx1 * wy0 * vx1 * vy0;
    float w10 = wx0 * wy1 * vx0 * vy1;
    float w11 = wx1 * wy1 * vx1 * vy1;
    int bHW = b * H * W * 64;
    int o00 = bHW + (y0c * W + x0c) * 64;
    int o01 = bHW + (y0c * W + x1c) * 64;
    int o10 = bHW + (y1c * W + x0c) * 64;
    int o11 = bHW + (y1c * W + x1c) * 64;
    int oout = bp * KFC_ + s * 64;

    int npts = M_ * NS_ - base;
    if (npts > 32) npts = 32;
    int l2 = lane * 2;
    for (int j = 0; j < npts; j++) {
        int a0 = __shfl_sync(0xffffffffu, o00, j);
        int a1 = __shfl_sync(0xffffffffu, o01, j);
        int a2 = __shfl_sync(0xffffffffu, o10, j);
        int a3 = __shfl_sync(0xffffffffu, o11, j);
        float q0 = __shfl_sync(0xffffffffu, w00, j);
        float q1 = __shfl_sync(0xffffffffu, w01, j);
        float q2 = __shfl_sync(0xffffffffu, w10, j);
        float q3 = __shfl_sync(0xffffffffu, w11, j);
        int oo = __shfl_sync(0xffffffffu, oout, j);
        float2 v0 = *(const float2*)(featT + a0 + l2);
        float2 v1 = *(const float2*)(featT + a1 + l2);
        float2 v2 = *(const float2*)(featT + a2 + l2);
        float2 v3 = *(const float2*)(featT + a3 + l2);
        float ax = q0 * v0.x + q1 * v1.x + q2 * v2.x + q3 * v3.x;
        float ay = q0 * v0.y + q1 * v1.y + q2 * v2.y + q3 * v3.y;
        __nv_bfloat16 h0 = __float2bfloat16(ax);
        __nv_bfloat16 h1 = __float2bfloat16(ay);
        __nv_bfloat16 l0 = __float2bfloat16(ax - __bfloat162float(h0));
        __nv_bfloat16 l1 = __float2bfloat16(ay - __bfloat162float(h1));
        __nv_bfloat162 hv; hv.x = h0; hv.y = h1;
        __nv_bfloat162 lv; lv.x = l0; lv.y = l1;
        *(__nv_bfloat162*)(Ahi + oo + l2) = hv;
        *(__nv_bfloat162*)(Alo + oo + l2) = lv;
    }
}

// ---------------- fc GEMM via mma.sync bf16, 3-term split, split-K=6 ----------------
#define LDA_S 24
#define LDB_S 72
__global__ void __launch_bounds__(128, 3) fc_mma_kernel(
    const __nv_bfloat16* __restrict__ Ahi, const __nv_bfloat16* __restrict__ Alo,
    const __nv_bfloat16* __restrict__ Bhi, const __nv_bfloat16* __restrict__ Blo,
    float* __restrict__ Cparts)
{
    __shared__ __align__(16) __nv_bfloat16 sAh[2][128 * LDA_S];
    __shared__ __align__(16) __nv_bfloat16 sAl[2][128 * LDA_S];
    __shared__ __align__(16) __nv_bfloat16 sBh[2][16 * LDB_S];
    __shared__ __align__(16) __nv_bfloat16 sBl[2][16 * LDB_S];

    int row0 = blockIdx.x * 128;
    int sk = blockIdx.y;
    int kbase = sk * (KFC_ / NSPLIT);
    const int NSTEP = KFC_ / NSPLIT / 16;  // 24
    int t = threadIdx.x;
    int lane = t & 31, w = t >> 5;

    float acc[2][8][4];
    #pragma unroll
    for (int mt = 0; mt < 2; mt++)
        #pragma unroll
        for (int nb = 0; nb < 8; nb++)
            #pragma unroll
            for (int q = 0; q < 4; q++) acc[mt][nb][q] = 0.0f;

    auto copy_tile = [&](int step, int buf) {
        int kk = kbase + step * 16;
        #pragma unroll
        for (int j = 0; j < 2; j++) {
            int idx = j * 128 + t;
            int r = idx >> 1, h = (idx & 1) * 8;
            size_t gsrc = (size_t)(row0 + r) * KFC_ + kk + h;
            cpasync16(smem_u32(&sAh[buf][r * LDA_S + h]), Ahi + gsrc);
            cpasync16(smem_u32(&sAl[buf][r * LDA_S + h]), Alo + gsrc);
        }
        {
            int r = t >> 3, cc = (t & 7) * 8;
            size_t gsrc = (size_t)(kk + r) * 64 + cc;
            cpasync16(smem_u32(&sBh[buf][r * LDB_S + cc]), Bhi + gsrc);
            cpasync16(smem_u32(&sBl[buf][r * LDB_S + cc]), Blo + gsrc);
        }
    };

    copy_tile(0, 0); cpcommit();

    int arow_off = (w * 32 + (lane & 15)) * LDA_S + (lane >> 4) * 8;
    int brow_base = (lane & 15) * LDB_S + (lane >> 4) * 8;

    for (int s = 0; s < NSTEP; s++) {
        int buf = s & 1;
        if (s < NSTEP - 1) { copy_tile(s + 1, buf ^ 1); cpcommit(); cpwait<1>(); }
        else               { cpwait<0>(); }
        __syncthreads();

        uint32_t ah[2][4], al[2][4], bh[8][2], bl[8][2];
        ldsm4(ah[0], smem_u32(&sAh[buf][arow_off]));
        ldsm4(ah[1], smem_u32(&sAh[buf][arow_off + 16 * LDA_S]));
        ldsm4(al[0], smem_u32(&sAl[buf][arow_off]));
        ldsm4(al[1], smem_u32(&sAl[buf][arow_off + 16 * LDA_S]));
        #pragma unroll
        for (int nb16 = 0; nb16 < 4; nb16++) {
            uint32_t rr[4];
            ldsm4t(rr, smem_u32(&sBh[buf][brow_base + nb16 * 16]));
            bh[nb16 * 2][0] = rr[0]; bh[nb16 * 2][1] = rr[1];
            bh[nb16 * 2 + 1][0] = rr[2]; bh[nb16 * 2 + 1][1] = rr[3];
            ldsm4t(rr, smem_u32(&sBl[buf][brow_base + nb16 * 16]));
            bl[nb16 * 2][0] = rr[0]; bl[nb16 * 2][1] = rr[1];
            bl[nb16 * 2 + 1][0] = rr[2]; bl[nb16 * 2 + 1][1] = rr[3];
        }
        #pragma unroll
        for (int mt = 0; mt < 2; mt++)
            #pragma unroll
            for (int nb = 0; nb < 8; nb++) {
                mma16816(acc[mt][nb], ah[mt], bh[nb]);
                mma16816(acc[mt][nb], ah[mt], bl[nb]);
                mma16816(acc[mt][nb], al[mt], bh[nb]);
            }
        __syncthreads();
    }

    float* Cp = Cparts + (size_t)sk * M_ * 64;
    #pragma unroll
    for (int mt = 0; mt < 2; mt++) {
        int r = row0 + w * 32 + mt * 16 + (lane >> 2);
        #pragma unroll
        for (int nb = 0; nb < 8; nb++) {
            int c = nb * 8 + (lane & 3) * 2;
            float2 v0; v0.x = acc[mt][nb][0]; v0.y = acc[mt][nb][1];
            float2 v1; v1.x = acc[mt][nb][2]; v1.y = acc[mt][nb][3];
            *(float2*)&Cp[(size_t)r * 64 + c] = v0;
            *(float2*)&Cp[(size_t)(r + 8) * 64 + c] = v1;
        }
    }
}

// ---------------- qkvF: combine split-K + bias/relu/tt -> F ; QKV = F @ Wqkv ----------------
#define QKVF_SMEM_FLOATS (4352 + 64 * 196)
__global__ void __launch_bounds__(256, 1) qkvF_kernel(
    const float* __restrict__ Cparts, const float* __restrict__ bias,
    const float* __restrict__ tt, const float* __restrict__ Wqkv,
    float* __restrict__ F, float* __restrict__ QKV)
{
    extern __shared__ float sm[];
    float* Ftr = sm;          // [64][68] : Ftr[k][m]
    float* Ws  = sm + 4352;   // [64][196]

    int row0 = blockIdx.x * 64;
    int b = row0 / NP_;
    int t = threadIdx.x;
    int tx = t & 15, ty = t >> 4;

    #pragma unroll
    for (int g = 0; g < 4; g++) {
        int idx = g * 256 + t;
        int m = idx >> 4;
        int n4 = (idx & 15) * 4;
        size_t off = (size_t)(row0 + m) * 64 + n4;
        float4 p = *(const float4*)(Cparts + off);
        #pragma unroll
        for (int sk = 1; sk < NSPLIT; sk++) {
            float4 q = *(const float4*)(Cparts + off + (size_t)sk * M_ * 64);
            p.x += q.x; p.y += q.y; p.z += q.z; p.w += q.w;
        }
        float4 bs = *(const float4*)(bias + n4);
        float4 tv = *(const float4*)(tt + b * 64 + n4);
        float4 o;
        o.x = fmaxf(p.x + bs.x, 0.0f) + tv.x;
        o.y = fmaxf(p.y + bs.y, 0.0f) + tv.y;
        o.z = fmaxf(p.z + bs.z, 0.0f) + tv.z;
        o.w = fmaxf(p.w + bs.w, 0.0f) + tv.w;
        *(float4*)(F + off) = o;
        Ftr[(n4 + 0) * 68 + m] = o.x;
        Ftr[(n4 + 1) * 68 + m] = o.y;
        Ftr[(n4 + 2) * 68 + m] = o.z;
        Ftr[(n4 + 3) * 68 + m] = o.w;
    }
    for (int idx = t; idx < 64 * 192; idx += 256) {
        int k = idx / 192, n = idx - k * 192;
        Ws[k * 196 + n] = Wqkv[idx];
    }
    __syncthreads();

    float acc[4][12];
    #pragma unroll
    for (int i = 0; i < 4; i++)
        #pragma unroll
        for (int j = 0; j < 12; j++) acc[i][j] = 0.0f;
    for (int k = 0; k < 64; k++) {
        float4 a4 = *(const float4*)&Ftr[k * 68 + ty * 4];
        float a[4] = {a4.x, a4.y, a4.z, a4.w};
        float4 b0 = *(const float4*)&Ws[k * 196 + tx * 12];
        float4 b1 = *(const float4*)&Ws[k * 196 + tx * 12 + 4];
        float4 b2 = *(const float4*)&Ws[k * 196 + tx * 12 + 8];
        float bb[12] = {b0.x,b0.y,b0.z,b0.w, b1.x,b1.y,b1.z,b1.w, b2.x,b2.y,b2.z,b2.w};
        #pragma unroll
        for (int i = 0; i < 4; i++)
            #pragma unroll
            for (int j = 0; j < 12; j++) acc[i][j] += a[i] * bb[j];
    }
    #pragma unroll
    for (int i = 0; i < 4; i++) {
        int m = row0 + ty * 4 + i;
        #pragma unroll
        for (int j = 0; j < 12; j++)
            QKV[(size_t)m * 192 + tx * 12 + j] = acc[i][j];
    }
}

// ---------------- fused attention ----------------
#define ATT_SMEM_FLOATS 32000
__global__ void __launch_bounds__(256, 1) attn_fused_kernel(
    const float* __restrict__ QKV, const float* __restrict__ Wo,
    const float* __restrict__ F, const float* __restrict__ scl, const float* __restrict__ shf,
    float* __restrict__ F2)
{
    extern __shared__ float sm[];
    float* QT  = sm;            // [64][68]
    float* KT  = sm + 4352;     // [64][196]
    float* Vs  = sm + 16896;    // [192][68]
    float* red = sm + 29952;
    float* red2= sm + 30976;

    int bid = blockIdx.x;
    int b = bid / 3;
    int row0 = (bid % 3) * 64;
    int t = threadIdx.x;
    int tx = t & 15, ty = t >> 4;
    const float* qkvb = QKV + (size_t)b * NP_ * 192;

    for (int idx = t; idx < 4096; idx += 256) {
        int r = idx >> 6, d = idx & 63;
        QT[d * 68 + r] = qkvb[(size_t)(row0 + r) * 192 + d];
    }
    for (int idx = t; idx < 12288; idx += 256) {
        int n = idx >> 6, d = idx & 63;
        KT[d * 196 + n] = qkvb[(size_t)n * 192 + 64 + d];
    }
    for (int idx = t; idx < 12288; idx += 256) {
        int k = idx >> 6, n = idx & 63;
        Vs[k * 68 + n] = qkvb[(size_t)k * 192 + 128 + n];
    }
    __syncthreads();

    float acc[4][12];
    #pragma unroll
    for (int i = 0; i < 4; i++)
        #pragma unroll
        for (int j = 0; j < 12; j++) acc[i][j] = 0.0f;
    for (int d = 0; d < 64; d++) {
        float4 a4 = *(const float4*)&QT[d * 68 + ty * 4];
        float a[4] = {a4.x, a4.y, a4.z, a4.w};
        float4 b0 = *(const float4*)&KT[d * 196 + tx * 12];
        float4 b1 = *(const float4*)&KT[d * 196 + tx * 12 + 4];
        float4 b2 = *(const float4*)&KT[d * 196 + tx * 12 + 8];
        float bb[12] = {b0.x,b0.y,b0.z,b0.w, b1.x,b1.y,b1.z,b1.w, b2.x,b2.y,b2.z,b2.w};
        #pragma unroll
        for (int i = 0; i < 4; i++)
            #pragma unroll
            for (int j = 0; j < 12; j++) acc[i][j] += a[i] * bb[j];
    }
    #pragma unroll
    for (int i = 0; i < 4; i++) {
        float m = -1e30f;
        #pragma unroll
        for (int j = 0; j < 12; j++) { acc[i][j] *= 0.125f; m = fmaxf(m, acc[i][j]); }
        red[(ty * 4 + i) * 16 + tx] = m;
    }
    __syncthreads();
    float inv_[4];
    #pragma unroll
    for (int i = 0; i < 4; i++) {
        int r = ty * 4 + i;
        float rm = red[r * 16];
        #pragma unroll
        for (int x = 1; x < 16; x++) rm = fmaxf(rm, red[r * 16 + x]);
        float s = 0.0f;
        #pragma unroll
        for (int j = 0; j < 12; j++) { acc[i][j] = expf(acc[i][j] - rm); s += acc[i][j]; }
        red2[r * 16 + tx] = s;
    }
    __syncthreads();
    #pragma unroll
    for (int i = 0; i < 4; i++) {
        int r = ty * 4 + i;
        float rs = red2[r * 16];
        #pragma unroll
        for (int x = 1; x < 16; x++) rs += red2[r * 16 + x];
        inv_[i] = 1.0f / rs;
    }
    #pragma unroll
    for (int i = 0; i < 4; i++)
        #pragma unroll
        for (int j = 0; j < 12; j++)
            KT[(ty * 4 + i) * 196 + tx * 12 + j] = acc[i][j] * inv_[i];
    __syncthreads();

    float acc2[4][4];
    #pragma unroll
    for (int i = 0; i < 4; i++)
        #pragma unroll
        for (int j = 0; j < 4; j++) acc2[i][j] = 0.0f;
    for (int k = 0; k < 192; k++) {
        float4 b4 = *(const float4*)&Vs[k * 68 + tx * 4];
        #pragma unroll
        for (int i = 0; i < 4; i++) {
            float a = KT[(ty * 4 + i) * 196 + k];
            acc2[i][0] += a * b4.x; acc2[i][1] += a * b4.y;
            acc2[i][2] += a * b4.z; acc2[i][3] += a * b4.w;
        }
    }
    __syncthreads();
    #pragma unroll
    for (int i = 0; i < 4; i++)
        #pragma unroll
        for (int j = 0; j < 4; j++)
            QT[(ty * 4 + i) * 68 + tx * 4 + j] = acc2[i][j];
    for (int idx = t; idx < 4096; idx += 256) {
        int k = idx >> 6, n = idx & 63;
        Vs[k * 68 + n] = Wo[idx];
    }
    __syncthreads();

    float acc3[4][4];
    #pragma unroll
    for (int i = 0; i < 4; i++)
        #pragma unroll
        for (int j = 0; j < 4; j++) acc3[i][j] = 0.0f;
    for (int k = 0; k < 64; k++) {
        float4 b4 = *(const float4*)&Vs[k * 68 + tx * 4];
        #pragma unroll
        for (int i = 0; i < 4; i++) {
            float a = QT[(ty * 4 + i) * 68 + k];
            acc3[i][0] += a * b4.x; acc3[i][1] += a * b4.y;
            acc3[i][2] += a * b4.z; acc3[i][3] += a * b4.w;
        }
    }
    #pragma unroll
    for (int i = 0; i < 4; i++) {
        int tok = b * NP_ + row0 + ty * 4 + i;
        #pragma unroll
        for (int j = 0; j < 4; j++) {
            int n = tx * 4 + j;
            float v = acc3[i][j] + F[(size_t)tok * 64 + n];
            v = v * (scl[b * 64 + n] + 1.0f) + shf[b * 64 + n];
            F2[(size_t)tok * 64 + n] = v;
        }
    }
}

// ---------------- fused tail ----------------
#define TAIL_SMEM_FLOATS 13824
__global__ void __launch_bounds__(256, 1) tail_fused_kernel(
    const float* __restrict__ F2,
    const float* __restrict__ Wc1, const float* __restrict__ bc1,
    const float* __restrict__ Wc2, const float* __restrict__ bc2,
    const float* __restrict__ Wcls, const float* __restrict__ bcls,
    const float* __restrict__ Wr1, const float* __restrict__ br1,
    const float* __restrict__ Wr2, const float* __restrict__ br2,
    const float* __restrict__ Wreg, const float* __restrict__ breg,
    float* __restrict__ anchor, float* __restrict__ sxs, float* __restrict__ out)
{
    extern __shared__ float sm[];
    float* X  = sm;           // [32][68]
    float* T1 = sm + 2176;
    float* T2 = sm + 4352;
    float* Wb = sm + 6528;
    float* RG = sm + 11392;

    int row0 = blockIdx.x * 32;
    int t = threadIdx.x;
    int tx = t & 15, ty = t >> 4;

    for (int idx = t; idx < 2048; idx += 256) {
        int r = idx >> 6, n = idx & 63;
        X[r * 68 + n] = F2[(size_t)(row0 + r) * 64 + n];
    }
    for (int idx = t; idx < 4096; idx += 256)
        Wb[(idx >> 6) * 68 + (idx & 63)] = Wc1[idx];
    __syncthreads();

#define MM64(IN, OUT, BIAS)                                                    \
    {                                                                          \
        float a0, a1; float ac[2][4];                                          \
        ac[0][0]=ac[0][1]=ac[0][2]=ac[0][3]=0.0f;                              \
        ac[1][0]=ac[1][1]=ac[1][2]=ac[1][3]=0.0f;                              \
        for (int k = 0; k < 64; k++) {                                         \
            float4 b4 = *(const float4*)&Wb[k * 68 + tx * 4];                  \
            a0 = IN[(ty * 2 + 0) * 68 + k];                                    \
            a1 = IN[(ty * 2 + 1) * 68 + k];                                    \
            ac[0][0]+=a0*b4.x; ac[0][1]+=a0*b4.y; ac[0][2]+=a0*b4.z; ac[0][3]+=a0*b4.w; \
            ac[1][0]+=a1*b4.x; ac[1][1]+=a1*b4.y; ac[1][2]+=a1*b4.z; ac[1][3]+=a1*b4.w; \
        }                                                                      \
        for (int i = 0; i < 2; i++)                                            \
            for (int j = 0; j < 4; j++) {                                      \
                int n = tx * 4 + j;                                            \
                OUT[(ty * 2 + i) * 68 + n] = fmaxf(ac[i][j] + BIAS[n], 0.0f);  \
            }                                                                  \
    }

    MM64(X, T1, bc1);
    __syncthreads();
    for (int idx = t; idx < 4096; idx += 256)
        Wb[(idx >> 6) * 68 + (idx & 63)] = Wc2[idx];
    __syncthreads();
    MM64(T1, T2, bc2);
    __syncthreads();

    if (t < 64) {
        int r = t >> 1, c = t & 1;
        float s = bcls[c];
        #pragma unroll 8
        for (int k = 0; k < 64; k++) s += T2[r * 68 + k] * Wcls[k * 2 + c];
        out[(size_t)(row0 + r) * OUTW_ + c] = s;
    }
    for (int idx = t; idx < 4096; idx += 256)
        Wb[(idx >> 6) * 68 + (idx & 63)] = Wr1[idx];
    __syncthreads();
    MM64(X, T1, br1);
    __syncthreads();
    for (int idx = t; idx < 4096; idx += 256)
        Wb[(idx >> 6) * 68 + (idx & 63)] = Wr2[idx];
    __syncthreads();
    MM64(T1, T2, br2);
    __syncthreads();
    for (int idx = t; idx < 64 * 76; idx += 256) Wb[idx] = Wreg[idx];
    __syncthreads();
    for (int idx = t; idx < 32 * 76; idx += 256) {
        int r = idx / 76, n = idx - r * 76;
        float s = breg[n];
        #pragma unroll 8
        for (int k = 0; k < 64; k++) s += T2[r * 68 + k] * Wb[k * 76 + n];
        RG[idx] = s;
    }
    __syncthreads();

    if (t < 32) {
        int bp = row0 + t;
        const float* rg = &RG[t * 76];
        float sy = anchor[bp * 3 + 0] + rg[0];
        float sx = anchor[bp * 3 + 1] + rg[1];
        float th = anchor[bp * 3 + 2] + rg[2];
        anchor[bp * 3 + 0] = sy;
        anchor[bp * 3 + 1] = sx;
        anchor[bp * 3 + 2] = th;
        float tan_t = tanf(th * PI_F);
        float ts = (fabsf(tan_t) < 0.001f) ? 0.001f : tan_t;
        float coef = 0.4f / ts;
        float* o = out + (size_t)bp * OUTW_;
        o[2] = sy; o[3] = sx; o[4] = th;
        o[5] = rg[3];
        #pragma unroll 8
        for (int r = 0; r < NR_; r++) {
            float xr = sx + ((float)r * (1.0f / 71.0f) - sy) * coef;
            o[6 + r] = xr + rg[4 + r];
        }
        #pragma unroll
        for (int s = 0; s < NS_; s++) {
            int idx = SIDX(35 - s);
            sxs[bp * NS_ + s] = sx + ((float)idx * (1.0f / 71.0f) - sy) * coef;
        }
    }
#undef MM64
}

// ---------------- host ----------------
extern "C" void kernel_launch(void* const* d_in, const int* in_sizes, int n_in,
                              void* d_out, int out_size)
{
    const float *feat0 = nullptr, *feat1 = nullptr, *feat2 = nullptr, *inputs = nullptr;
    const int* tarr = nullptr;
    const float *W_t1 = nullptr, *b_t1 = nullptr, *W_t2 = nullptr, *b_t2 = nullptr;
    const float *W_st = nullptr, *b_st = nullptr, *W_tc = nullptr, *b_tc = nullptr;
    const float *W_fc = nullptr, *b_fc = nullptr;
    const float *W_q = nullptr, *W_k = nullptr, *W_v = nullptr, *W_o = nullptr;
    const float *W_c1 = nullptr, *b_c1 = nullptr, *W_c2 = nullptr, *b_c2 = nullptr;
    const float *W_r1 = nullptr, *b_r1 = nullptr, *W_r2 = nullptr, *b_r2 = nullptr;
    const float *W_cls = nullptr, *b_cls = nullptr, *W_reg = nullptr, *b_reg = nullptr;

    int idx16384 = 0, idx4096 = 0, idx256 = 0, idx64 = 0;
    int idxWst = -1;
    int idx128_pos[2] = {-1, -1}; int n128 = 0;
    const float* p4096[8] = {0};
    const float* p64[6] = {0};

    for (int i = 0; i < n_in; i++) {
        const float* p = (const float*)d_in[i];
        switch (in_sizes[i]) {
            case 8192000: feat0 = p; break;
            case 2048000: feat1 = p; break;
            case 512000:  feat2 = p; break;
            case 18432:   inputs = p; break;
            case 32:      tarr = (const int*)d_in[i]; break;
            case 65536:   W_t2 = p; break;
            case 32768:   W_st = p; idxWst = i; break;
            case 147456:  W_fc = p; break;
            case 4864:    W_reg = p; break;
            case 2:       b_cls = p; break;
            case 76:      b_reg = p; break;
            case 16384:   if (idx16384++ == 0) W_t1 = p; else W_tc = p; break;
            case 4096:    if (idx4096 < 8) p4096[idx4096++] = p; break;
            case 256:     if (idx256++ == 0) b_t1 = p; else b_t2 = p; break;
            case 64:      if (idx64 < 6) p64[idx64++] = p; break;
            case 128:     if (n128 < 2) idx128_pos[n128++] = i; break;
            default: break;
        }
    }
    W_q = p4096[0]; W_k = p4096[1]; W_v = p4096[2]; W_o = p4096[3];
    W_c1 = p4096[4]; W_c2 = p4096[5]; W_r1 = p4096[6]; W_r2 = p4096[7];
    b_tc = p64[0]; b_fc = p64[1]; b_c1 = p64[2]; b_c2 = p64[3]; b_r1 = p64[4]; b_r2 = p64[5];
    if (n128 == 2) {
        if (idx128_pos[0] == idxWst + 1) {
            b_st  = (const float*)d_in[idx128_pos[0]];
            W_cls = (const float*)d_in[idx128_pos[1]];
        } else if (idx128_pos[1] == idxWst + 1) {
            b_st  = (const float*)d_in[idx128_pos[1]];
            W_cls = (const float*)d_in[idx128_pos[0]];
        } else {
            W_cls = (const float*)d_in[idx128_pos[0]];
            b_st  = (const float*)d_in[idx128_pos[1]];
        }
    }

    static int attr_done = 0;
    if (!attr_done) {
        cudaFuncSetAttribute(attn_fused_kernel, cudaFuncAttributeMaxDynamicSharedMemorySize,
                             ATT_SMEM_FLOATS * 4);
        cudaFuncSetAttribute(tail_fused_kernel, cudaFuncAttributeMaxDynamicSharedMemorySize,
                             TAIL_SMEM_FLOATS * 4);
        cudaFuncSetAttribute(qkvF_kernel, cudaFuncAttributeMaxDynamicSharedMemorySize,
                             QKVF_SMEM_FLOATS * 4);
        attr_done = 1;
    }

    float* S;
    cudaGetSymbolAddress((void**)&S, g_scratch);
    float* f0T = S + O_F0T;  float* f1T = S + O_F1T;  float* f2T = S + O_F2T;
    __nv_bfloat16* gAhi = (__nv_bfloat16*)(S + O_AHI);
    __nv_bfloat16* gAlo = (__nv_bfloat16*)(S + O_ALO);
    __nv_bfloat16* gBhi = (__nv_bfloat16*)(S + O_BHI);
    __nv_bfloat16* gBlo = (__nv_bfloat16*)(S + O_BLO);
    float* Wqkv = S + O_WQKV;
    float* gF = S + O_F; float* gF2 = S + O_F2; float* gQKV = S + O_QKV;
    float* gCP = S + O_CPART;
    float* gANCH = S + O_ANCH; float* gSXS = S + O_SXS;
    float* gTT = S + O_TT; float* gSCL = S + O_SCALE; float* gSHF = S + O_SHIFT;
    float* outP = (float*)d_out;

    const float* feats[3] = { f2T, f1T, f0T };
    const int Hs[3] = { 10, 20, 40 };
    const int Ws_[3] = { 25, 50, 100 };
    int gsBlocks = (M_ * NS_ + 32 * 8 - 1) / (32 * 8);   // 32 pts/warp, 8 warps/CTA

    // launch order: slot 4 = gridsample (ncu profiled slot)
    setup_misc_kernel<<<680, 256>>>(W_fc, gBhi, gBlo, W_q, W_k, W_v, Wqkv,
                                    inputs, gANCH, gSXS,
                                    tarr, W_t1, b_t1, W_t2, b_t2, W_st, b_st,
                                    W_tc, b_tc, gTT, gSCL, gSHF);                     // 1
    transpose_f0_kernel<<<dim3(125, 2, B_), dim3(32, 8)>>>(feat0, f0T);               // 2
    transpose_f12_kernel<<<dim3(40, 2, B_), dim3(32, 8)>>>(feat1, f1T, feat2, f2T);   // 3
    gridsample_kernel<<<gsBlocks, 256>>>(feats[0], Hs[0], Ws_[0], gSXS, gAhi, gAlo);  // 4 [prof]
    fc_mma_kernel<<<dim3(48, NSPLIT), 128>>>(gAhi, gAlo, gBhi, gBlo, gCP);            // 5

    for (int it = 0; it < 3; it++) {
        if (it > 0) {
            gridsample_kernel<<<gsBlocks, 256>>>(feats[it], Hs[it], Ws_[it], gSXS, gAhi, gAlo);
            fc_mma_kernel<<<dim3(48, NSPLIT), 128>>>(gAhi, gAlo, gBhi, gBlo, gCP);
        }
        qkvF_kernel<<<M_ / 64, 256, QKVF_SMEM_FLOATS * 4>>>(gCP, b_fc, gTT, Wqkv, gF, gQKV);
        attn_fused_kernel<<<B_ * 3, 256, ATT_SMEM_FLOATS * 4>>>(gQKV, W_o, gF, gSCL, gSHF, gF2);
        tail_fused_kernel<<<M_ / 32, 256, TAIL_SMEM_FLOATS * 4>>>(
            gF2, W_c1, b_c1, W_c2, b_c2, W_cls, b_cls, W_r1, b_r1, W_r2, b_r2,
            W_reg, b_reg, gANCH, gSXS, outP);
    }
    (void)out_size; (void)n_in;
}

// round 10
// speedup vs baseline: 1.1141x; 1.0603x over previous
#include <cuda_runtime.h>
#include <cuda_bf16.h>
#include <math.h>
#include <stdint.h>

// ---------------- problem constants ----------------
#define B_   32
#define NP_  192
#define NR_  72
#define NS_  36
#define FC_  64
#define M_   (B_*NP_)        // 6144
#define KFC_ (FC_*NS_)       // 2304
#define OUTW_ 78
#define PI_F 3.14159265358979323846f
#define NSPLIT 6

__device__ __forceinline__ int SIDX(int i) { return (i < 35) ? 2*i : 71; }

// ---------------- scratch offsets (floats) ----------------
#define O_F0T   0UL
#define O_F1T   8192000UL
#define O_F2T   10240000UL
#define O_AHI   10752000UL   // bf16 [6144][2304]
#define O_ALO   17829888UL
#define O_BHI   24907776UL   // bf16 [2304][64]
#define O_BLO   24981504UL
#define O_WQKV  25055232UL
#define O_F     25067520UL
#define O_F2    25460736UL
#define O_QKV   25853952UL   // 6144*192
#define O_CPART 27033600UL   // 6 x 6144 x 64 fp32
#define O_ANCH  29392896UL
#define O_SXS   29411328UL
#define O_TT    29632512UL
#define O_SCALE 29634560UL
#define O_SHIFT 29636608UL
#define SCRATCH_FLOATS 29638656UL

__device__ float g_scratch[SCRATCH_FLOATS];

// ---------------- PTX helpers ----------------
__device__ __forceinline__ uint32_t smem_u32(const void* p) {
    uint32_t a;
    asm("{ .reg .u64 t; cvta.to.shared.u64 t, %1; cvt.u32.u64 %0, t; }" : "=r"(a) : "l"(p));
    return a;
}
__device__ __forceinline__ void ldsm4(uint32_t* r, uint32_t addr) {
    asm volatile("ldmatrix.sync.aligned.m8n8.x4.shared.b16 {%0,%1,%2,%3}, [%4];"
        : "=r"(r[0]), "=r"(r[1]), "=r"(r[2]), "=r"(r[3]) : "r"(addr));
}
__device__ __forceinline__ void ldsm4t(uint32_t* r, uint32_t addr) {
    asm volatile("ldmatrix.sync.aligned.m8n8.x4.trans.shared.b16 {%0,%1,%2,%3}, [%4];"
        : "=r"(r[0]), "=r"(r[1]), "=r"(r[2]), "=r"(r[3]) : "r"(addr));
}
__device__ __forceinline__ void mma16816(float* c, const uint32_t* a, const uint32_t* b) {
    asm volatile("mma.sync.aligned.m16n8k16.row.col.f32.bf16.bf16.f32 "
        "{%0,%1,%2,%3}, {%4,%5,%6,%7}, {%8,%9}, {%0,%1,%2,%3};"
        : "+f"(c[0]), "+f"(c[1]), "+f"(c[2]), "+f"(c[3])
        : "r"(a[0]), "r"(a[1]), "r"(a[2]), "r"(a[3]), "r"(b[0]), "r"(b[1]));
}
__device__ __forceinline__ void cpasync16(uint32_t dst, const void* src) {
    asm volatile("cp.async.cg.shared.global [%0], [%1], 16;" :: "r"(dst), "l"(src));
}
__device__ __forceinline__ void cpcommit() {
    asm volatile("cp.async.commit_group;" ::: "memory");
}
template<int N> __device__ __forceinline__ void cpwait() {
    asm volatile("cp.async.wait_group %0;" :: "n"(N) : "memory");
}

__device__ __forceinline__ float gelu_tanh(float x) {
    float x3 = x * x * x;
    return 0.5f * x * (1.0f + tanhf(0.7978845608028654f * (x + 0.044715f * x3)));
}
__device__ __forceinline__ float sigmoidf_(float x) { return 1.0f / (1.0f + expf(-x)); }

// ---------------- merged setup: pack_wb | pack_wqkv | init_anchor | time_mlp ----------------
__global__ void setup_misc_kernel(
    const float* __restrict__ Wfc,
    __nv_bfloat16* __restrict__ Bhi, __nv_bfloat16* __restrict__ Blo,
    const float* __restrict__ Wq, const float* __restrict__ Wk,
    const float* __restrict__ Wv, float* __restrict__ Wqkv,
    const float* __restrict__ inp, float* __restrict__ anchor, float* __restrict__ sxs,
    const int* __restrict__ tarr,
    const float* __restrict__ Wt1, const float* __restrict__ bt1,
    const float* __restrict__ Wt2, const float* __restrict__ bt2,
    const float* __restrict__ Wst, const float* __restrict__ bst,
    const float* __restrict__ Wtc, const float* __restrict__ btc,
    float* __restrict__ tt, float* __restrict__ scl, float* __restrict__ shf)
{
    __shared__ float se[64];
    __shared__ float h1[256];
    __shared__ float temb[256];
    __shared__ float tsil[256];
    int bx = blockIdx.x;
    int t = threadIdx.x;
    if (bx < 576) {
        int idx = bx * 256 + t;
        int k = idx >> 6, n = idx & 63;
        int c = k & 63, s = k >> 6;
        float v = Wfc[(c * 36 + s) * 64 + n];
        __nv_bfloat16 h = __float2bfloat16(v);
        __nv_bfloat16 l = __float2bfloat16(v - __bfloat162float(h));
        Bhi[idx] = h;
        Blo[idx] = l;
    } else if (bx < 624) {
        int idx = (bx - 576) * 256 + t;
        int k = idx / 192, n = idx % 192;
        float v;
        if (n < 64)        v = Wq[k * 64 + n];
        else if (n < 128)  v = Wk[k * 64 + (n - 64)];
        else               v = Wv[k * 64 + (n - 128)];
        Wqkv[idx] = v;
    } else if (bx < 648) {
        int bp = (bx - 624) * 256 + t;
        float sy = inp[bp * 3 + 0];
        float sx = inp[bp * 3 + 1];
        float th = inp[bp * 3 + 2];
        anchor[bp * 3 + 0] = sy;
        anchor[bp * 3 + 1] = sx;
        anchor[bp * 3 + 2] = th;
        float tan_t = tanf(th * PI_F);
        float ts = (fabsf(tan_t) < 0.001f) ? 0.001f : tan_t;
        float coef = 0.4f / ts;
        #pragma unroll
        for (int s = 0; s < NS_; s++) {
            int idx = SIDX(35 - s);
            sxs[bp * NS_ + s] = sx + ((float)idx * (1.0f / 71.0f) - sy) * coef;
        }
    } else {
        int b = bx - 648;
        float tv = (float)tarr[b];
        if (t < 64) {
            int i = (t < 32) ? t : t - 32;
            float factor = -logf(10000.0f) / 31.0f;
            float ang = tv * expf((float)i * factor);
            se[t] = (t < 32) ? sinf(ang) : cosf(ang);
        }
        __syncthreads();
        {
            float acc = bt1[t];
            #pragma unroll 8
            for (int k = 0; k < 64; k++) acc += se[k] * Wt1[k * 256 + t];
            h1[t] = gelu_tanh(acc);
        }
        __syncthreads();
        {
            float acc = bt2[t];
            for (int k = 0; k < 256; k++) acc += h1[k] * Wt2[k * 256 + t];
            temb[t] = acc;
            tsil[t] = acc * sigmoidf_(acc);
        }
        __syncthreads();
        if (t < 128) {
            float acc = bst[t];
            for (int k = 0; k < 256; k++) acc += tsil[k] * Wst[k * 128 + t];
            if (t < 64) scl[b * 64 + t] = acc;
            else        shf[b * 64 + (t - 64)] = acc;
        } else if (t < 192) {
            int m = t - 128;
            float acc = btc[m];
            for (int k = 0; k < 256; k++) acc += temb[k] * Wtc[k * 64 + m];
            tt[b * 64 + m] = acc;
        }
    }
}

// ---------------- transpose (B,C,HW)->(B,HW,C) ----------------
// f0+f1 combined (side stream); f2 separate (critical path)
__global__ void transpose_f01_kernel(const float* __restrict__ f0, float* __restrict__ o0,
                                     const float* __restrict__ f1, float* __restrict__ o1)
{
    __shared__ float tile[32][33];
    int bx = blockIdx.x;
    const float* in; float* out; int HW; int x0;
    if (bx < 125) { in = f0; out = o0; HW = 4000; x0 = bx * 32; }
    else          { in = f1; out = o1; HW = 1000; x0 = (bx - 125) * 32; }
    int b  = blockIdx.z;
    int c0 = blockIdx.y * 32;
    int tx = threadIdx.x, ty = threadIdx.y;
    const float* ib = in  + (size_t)b * 64 * HW;
    float*       ob = out + (size_t)b * HW * 64;
    #pragma unroll
    for (int j = ty; j < 32; j += 8) {
        int x = x0 + tx;
        if (x < HW) tile[j][tx] = ib[(c0 + j) * HW + x];
    }
    __syncthreads();
    #pragma unroll
    for (int j = ty; j < 32; j += 8) {
        int x = x0 + j;
        if (x < HW) ob[(size_t)x * 64 + c0 + tx] = tile[tx][j];
    }
}
__global__ void transpose_f2_kernel(const float* __restrict__ f2, float* __restrict__ o2)
{
    __shared__ float tile[32][33];
    int x0 = blockIdx.x * 32;
    int b  = blockIdx.z;
    int c0 = blockIdx.y * 32;
    int tx = threadIdx.x, ty = threadIdx.y;
    const int HW = 250;
    const float* ib = f2 + (size_t)b * 64 * HW;
    float*       ob = o2 + (size_t)b * HW * 64;
    #pragma unroll
    for (int j = ty; j < 32; j += 8) {
        int x = x0 + tx;
        if (x < HW) tile[j][tx] = ib[(c0 + j) * HW + x];
    }
    __syncthreads();
    #pragma unroll
    for (int j = ty; j < 32; j += 8) {
        int x = x0 + j;
        if (x < HW) ob[(size_t)x * 64 + c0 + tx] = tile[tx][j];
    }
}

// ---------------- grid sample v3: clamp-fold + half-warp float4 ----------------
// Warp owns 32 points (lane L computes params for point base+L). Loop j=0..15:
// half-warp 0 processes point j, half-warp 1 point j+16 (srcLane = j | (lane&16)).
// Corner addresses are o00 (+dx) (+dy) with dx,dy packed in one int; out-of-range
// corners have weight folded into valid corners, so every load is in-bounds.
__global__ void gridsample_kernel(const float* __restrict__ featT, int H, int W,
                                  const float* __restrict__ sxs,
                                  __nv_bfloat16* __restrict__ Ahi, __nv_bfloat16* __restrict__ Alo)
{
    int warp = (blockIdx.x * 256 + threadIdx.x) >> 5;
    int lane = threadIdx.x & 31;
    int base = warp * 32;                 // grid sized exactly: M_*NS_ % 32 == 0

    int wi = base + lane;
    int bp = wi / NS_;
    int s  = wi - bp * NS_;
    int b  = bp / NP_;
    float xx = sxs[bp * NS_ + s] * (float)(W - 1);
    float yy = ((float)SIDX(35 - s) * (1.0f / 71.0f)) * (float)(H - 1);
    float x0f = floorf(xx), y0f = floorf(yy);
    int x0 = (int)x0f, y0 = (int)y0f;
    float wx1 = xx - x0f, wx0 = 1.0f - wx1;
    float wy1 = yy - y0f, wy0 = 1.0f - wy1;
    float vx0 = (x0 >= 0 && x0 < W) ? 1.0f : 0.0f;
    float vx1 = (x0 >= -1 && x0 < W - 1) ? 1.0f : 0.0f;
    float vy0 = (y0 >= 0 && y0 < H) ? 1.0f : 0.0f;
    float vy1 = (y0 >= -1 && y0 < H - 1) ? 1.0f : 0.0f;
    float w00 = wx0 * wy0 * vx0 * vy0;
    float w01 = wx1 * wy0 * vx1 * vy0;
    float w10 = wx0 * wy1 * vx0 * vy1;
    float w11 = wx1 * wy1 * vx1 * vy1;
    if (x0 < 0) { w00 += w01; w01 = 0.0f; w10 += w11; w11 = 0.0f; }
    if (y0 < 0) { w00 += w10; w10 = 0.0f; w01 += w11; w11 = 0.0f; }
    int x0c = min(max(x0, 0), W - 1);
    int y0c = min(max(y0, 0), H - 1);
    int dx = (x0c < W - 1) ? 64 : 0;
    int dy = (y0c < H - 1) ? W * 64 : 0;
    int o00 = b * H * W * 64 + (y0c * W + x0c) * 64;
    int pck = dx | (dy << 16);
    int oout = bp * KFC_ + s * 64;

    int ch = (lane & 15) * 4;
    int hb = lane & 16;
    #pragma unroll 4
    for (int j = 0; j < 16; j++) {
        int src = j | hb;
        int a0 = __shfl_sync(0xffffffffu, o00, src);
        int pk = __shfl_sync(0xffffffffu, pck, src);
        float q0 = __shfl_sync(0xffffffffu, w00, src);
        float q1 = __shfl_sync(0xffffffffu, w01, src);
        float q2 = __shfl_sync(0xffffffffu, w10, src);
        float q3 = __shfl_sync(0xffffffffu, w11, src);
        int oo = __shfl_sync(0xffffffffu, oout, src);
        int ddx = pk & 0xffff, ddy = pk >> 16;
        float4 f00 = *(const float4*)(featT + a0 + ch);
        float4 f01 = *(const float4*)(featT + a0 + ddx + ch);
        float4 f10 = *(const float4*)(featT + a0 + ddy + ch);
        float4 f11 = *(const float4*)(featT + a0 + ddy + ddx + ch);
        float r0 = q0 * f00.x + q1 * f01.x + q2 * f10.x + q3 * f11.x;
        float r1 = q0 * f00.y + q1 * f01.y + q2 * f10.y + q3 * f11.y;
        float r2 = q0 * f00.z + q1 * f01.z + q2 * f10.z + q3 * f11.z;
        float r3 = q0 * f00.w + q1 * f01.w + q2 * f10.w + q3 * f11.w;
        __nv_bfloat16 h0 = __float2bfloat16(r0);
        __nv_bfloat16 h1 = __float2bfloat16(r1);
        __nv_bfloat16 h2 = __float2bfloat16(r2);
        __nv_bfloat16 h3 = __float2bfloat16(r3);
        union { __nv_bfloat162 b2[2]; uint2 u; } hu, lu;
        hu.b2[0].x = h0; hu.b2[0].y = h1; hu.b2[1].x = h2; hu.b2[1].y = h3;
        lu.b2[0].x = __float2bfloat16(r0 - __bfloat162float(h0));
        lu.b2[0].y = __float2bfloat16(r1 - __bfloat162float(h1));
        lu.b2[1].x = __float2bfloat16(r2 - __bfloat162float(h2));
        lu.b2[1].y = __float2bfloat16(r3 - __bfloat162float(h3));
        *(uint2*)(Ahi + oo + ch) = hu.u;
        *(uint2*)(Alo + oo + ch) = lu.u;
    }
}

// ---------------- fc GEMM via mma.sync bf16, 3-term split, split-K=6 ----------------
#define LDA_S 24
#define LDB_S 72
__global__ void __launch_bounds__(128, 3) fc_mma_kernel(
    const __nv_bfloat16* __restrict__ Ahi, const __nv_bfloat16* __restrict__ Alo,
    const __nv_bfloat16* __restrict__ Bhi, const __nv_bfloat16* __restrict__ Blo,
    float* __restrict__ Cparts)
{
    __shared__ __align__(16) __nv_bfloat16 sAh[2][128 * LDA_S];
    __shared__ __align__(16) __nv_bfloat16 sAl[2][128 * LDA_S];
    __shared__ __align__(16) __nv_bfloat16 sBh[2][16 * LDB_S];
    __shared__ __align__(16) __nv_bfloat16 sBl[2][16 * LDB_S];

    int row0 = blockIdx.x * 128;
    int sk = blockIdx.y;
    int kbase = sk * (KFC_ / NSPLIT);
    const int NSTEP = KFC_ / NSPLIT / 16;  // 24
    int t = threadIdx.x;
    int lane = t & 31, w = t >> 5;

    float acc[2][8][4];
    #pragma unroll
    for (int mt = 0; mt < 2; mt++)
        #pragma unroll
        for (int nb = 0; nb < 8; nb++)
            #pragma unroll
            for (int q = 0; q < 4; q++) acc[mt][nb][q] = 0.0f;

    auto copy_tile = [&](int step, int buf) {
        int kk = kbase + step * 16;
        #pragma unroll
        for (int j = 0; j < 2; j++) {
            int idx = j * 128 + t;
            int r = idx >> 1, h = (idx & 1) * 8;
            size_t gsrc = (size_t)(row0 + r) * KFC_ + kk + h;
            cpasync16(smem_u32(&sAh[buf][r * LDA_S + h]), Ahi + gsrc);
            cpasync16(smem_u32(&sAl[buf][r * LDA_S + h]), Alo + gsrc);
        }
        {
            int r = t >> 3, cc = (t & 7) * 8;
            size_t gsrc = (size_t)(kk + r) * 64 + cc;
            cpasync16(smem_u32(&sBh[buf][r * LDB_S + cc]), Bhi + gsrc);
            cpasync16(smem_u32(&sBl[buf][r * LDB_S + cc]), Blo + gsrc);
        }
    };

    copy_tile(0, 0); cpcommit();

    int arow_off = (w * 32 + (lane & 15)) * LDA_S + (lane >> 4) * 8;
    int brow_base = (lane & 15) * LDB_S + (lane >> 4) * 8;

    for (int s = 0; s < NSTEP; s++) {
        int buf = s & 1;
        if (s < NSTEP - 1) { copy_tile(s + 1, buf ^ 1); cpcommit(); cpwait<1>(); }
        else               { cpwait<0>(); }
        __syncthreads();

        uint32_t ah[2][4], al[2][4], bh[8][2], bl[8][2];
        ldsm4(ah[0], smem_u32(&sAh[buf][arow_off]));
        ldsm4(ah[1], smem_u32(&sAh[buf][arow_off + 16 * LDA_S]));
        ldsm4(al[0], smem_u32(&sAl[buf][arow_off]));
        ldsm4(al[1], smem_u32(&sAl[buf][arow_off + 16 * LDA_S]));
        #pragma unroll
        for (int nb16 = 0; nb16 < 4; nb16++) {
            uint32_t rr[4];
            ldsm4t(rr, smem_u32(&sBh[buf][brow_base + nb16 * 16]));
            bh[nb16 * 2][0] = rr[0]; bh[nb16 * 2][1] = rr[1];
            bh[nb16 * 2 + 1][0] = rr[2]; bh[nb16 * 2 + 1][1] = rr[3];
            ldsm4t(rr, smem_u32(&sBl[buf][brow_base + nb16 * 16]));
            bl[nb16 * 2][0] = rr[0]; bl[nb16 * 2][1] = rr[1];
            bl[nb16 * 2 + 1][0] = rr[2]; bl[nb16 * 2 + 1][1] = rr[3];
        }
        #pragma unroll
        for (int mt = 0; mt < 2; mt++)
            #pragma unroll
            for (int nb = 0; nb < 8; nb++) {
                mma16816(acc[mt][nb], ah[mt], bh[nb]);
                mma16816(acc[mt][nb], ah[mt], bl[nb]);
                mma16816(acc[mt][nb], al[mt], bh[nb]);
            }
        __syncthreads();
    }

    float* Cp = Cparts + (size_t)sk * M_ * 64;
    #pragma unroll
    for (int mt = 0; mt < 2; mt++) {
        int r = row0 + w * 32 + mt * 16 + (lane >> 2);
        #pragma unroll
        for (int nb = 0; nb < 8; nb++) {
            int c = nb * 8 + (lane & 3) * 2;
            float2 v0; v0.x = acc[mt][nb][0]; v0.y = acc[mt][nb][1];
            float2 v1; v1.x = acc[mt][nb][2]; v1.y = acc[mt][nb][3];
            *(float2*)&Cp[(size_t)r * 64 + c] = v0;
            *(float2*)&Cp[(size_t)(r + 8) * 64 + c] = v1;
        }
    }
}

// ---------------- qkvF: combine split-K + bias/relu/tt -> F ; QKV = F @ Wqkv ----------------
#define QKVF_SMEM_FLOATS (4352 + 64 * 196)
__global__ void __launch_bounds__(256, 1) qkvF_kernel(
    const float* __restrict__ Cparts, const float* __restrict__ bias,
    const float* __restrict__ tt, const float* __restrict__ Wqkv,
    float* __restrict__ F, float* __restrict__ QKV)
{
    extern __shared__ float sm[];
    float* Ftr = sm;          // [64][68] : Ftr[k][m]
    float* Ws  = sm + 4352;   // [64][196]

    int row0 = blockIdx.x * 64;
    int b = row0 / NP_;
    int t = threadIdx.x;
    int tx = t & 15, ty = t >> 4;

    #pragma unroll
    for (int g = 0; g < 4; g++) {
        int idx = g * 256 + t;
        int m = idx >> 4;
        int n4 = (idx & 15) * 4;
        size_t off = (size_t)(row0 + m) * 64 + n4;
        float4 p = *(const float4*)(Cparts + off);
        #pragma unroll
        for (int sk = 1; sk < NSPLIT; sk++) {
            float4 q = *(const float4*)(Cparts + off + (size_t)sk * M_ * 64);
            p.x += q.x; p.y += q.y; p.z += q.z; p.w += q.w;
        }
        float4 bs = *(const float4*)(bias + n4);
        float4 tv = *(const float4*)(tt + b * 64 + n4);
        float4 o;
        o.x = fmaxf(p.x + bs.x, 0.0f) + tv.x;
        o.y = fmaxf(p.y + bs.y, 0.0f) + tv.y;
        o.z = fmaxf(p.z + bs.z, 0.0f) + tv.z;
        o.w = fmaxf(p.w + bs.w, 0.0f) + tv.w;
        *(float4*)(F + off) = o;
        Ftr[(n4 + 0) * 68 + m] = o.x;
        Ftr[(n4 + 1) * 68 + m] = o.y;
        Ftr[(n4 + 2) * 68 + m] = o.z;
        Ftr[(n4 + 3) * 68 + m] = o.w;
    }
    for (int idx = t; idx < 64 * 192; idx += 256) {
        int k = idx / 192, n = idx - k * 192;
        Ws[k * 196 + n] = Wqkv[idx];
    }
    __syncthreads();

    float acc[4][12];
    #pragma unroll
    for (int i = 0; i < 4; i++)
        #pragma unroll
        for (int j = 0; j < 12; j++) acc[i][j] = 0.0f;
    for (int k = 0; k < 64; k++) {
        float4 a4 = *(const float4*)&Ftr[k * 68 + ty * 4];
        float a[4] = {a4.x, a4.y, a4.z, a4.w};
        float4 b0 = *(const float4*)&Ws[k * 196 + tx * 12];
        float4 b1 = *(const float4*)&Ws[k * 196 + tx * 12 + 4];
        float4 b2 = *(const float4*)&Ws[k * 196 + tx * 12 + 8];
        float bb[12] = {b0.x,b0.y,b0.z,b0.w, b1.x,b1.y,b1.z,b1.w, b2.x,b2.y,b2.z,b2.w};
        #pragma unroll
        for (int i = 0; i < 4; i++)
            #pragma unroll
            for (int j = 0; j < 12; j++) acc[i][j] += a[i] * bb[j];
    }
    #pragma unroll
    for (int i = 0; i < 4; i++) {
        int m = row0 + ty * 4 + i;
        #pragma unroll
        for (int j = 0; j < 12; j++)
            QKV[(size_t)m * 192 + tx * 12 + j] = acc[i][j];
    }
}

// ---------------- fused attention ----------------
#define ATT_SMEM_FLOATS 32000
__global__ void __launch_bounds__(256, 1) attn_fused_kernel(
    const float* __restrict__ QKV, const float* __restrict__ Wo,
    const float* __restrict__ F, const float* __restrict__ scl, const float* __restrict__ shf,
    float* __restrict__ F2)
{
    extern __shared__ float sm[];
    float* QT  = sm;            // [64][68]
    float* KT  = sm + 4352;     // [64][196]
    float* Vs  = sm + 16896;    // [192][68]
    float* red = sm + 29952;
    float* red2= sm + 30976;

    int bid = blockIdx.x;
    int b = bid / 3;
    int row0 = (bid % 3) * 64;
    int t = threadIdx.x;
    int tx = t & 15, ty = t >> 4;
    const float* qkvb = QKV + (size_t)b * NP_ * 192;

    for (int idx = t; idx < 4096; idx += 256) {
        int r = idx >> 6, d = idx & 63;
        QT[d * 68 + r] = qkvb[(size_t)(row0 + r) * 192 + d];
    }
    for (int idx = t; idx < 12288; idx += 256) {
        int n = idx >> 6, d = idx & 63;
        KT[d * 196 + n] = qkvb[(size_t)n * 192 + 64 + d];
    }
    for (int idx = t; idx < 12288; idx += 256) {
        int k = idx >> 6, n = idx & 63;
        Vs[k * 68 + n] = qkvb[(size_t)k * 192 + 128 + n];
    }
    __syncthreads();

    float acc[4][12];
    #pragma unroll
    for (int i = 0; i < 4; i++)
        #pragma unroll
        for (int j = 0; j < 12; j++) acc[i][j] = 0.0f;
    for (int d = 0; d < 64; d++) {
        float4 a4 = *(const float4*)&QT[d * 68 + ty * 4];
        float a[4] = {a4.x, a4.y, a4.z, a4.w};
        float4 b0 = *(const float4*)&KT[d * 196 + tx * 12];
        float4 b1 = *(const float4*)&KT[d * 196 + tx * 12 + 4];
        float4 b2 = *(const float4*)&KT[d * 196 + tx * 12 + 8];
        float bb[12] = {b0.x,b0.y,b0.z,b0.w, b1.x,b1.y,b1.z,b1.w, b2.x,b2.y,b2.z,b2.w};
        #pragma unroll
        for (int i = 0; i < 4; i++)
            #pragma unroll
            for (int j = 0; j < 12; j++) acc[i][j] += a[i] * bb[j];
    }
    #pragma unroll
    for (int i = 0; i < 4; i++) {
        float m = -1e30f;
        #pragma unroll
        for (int j = 0; j < 12; j++) { acc[i][j] *= 0.125f; m = fmaxf(m, acc[i][j]); }
        red[(ty * 4 + i) * 16 + tx] = m;
    }
    __syncthreads();
    float inv_[4];
    #pragma unroll
    for (int i = 0; i < 4; i++) {
        int r = ty * 4 + i;
        float rm = red[r * 16];
        #pragma unroll
        for (int x = 1; x < 16; x++) rm = fmaxf(rm, red[r * 16 + x]);
        float s = 0.0f;
        #pragma unroll
        for (int j = 0; j < 12; j++) { acc[i][j] = expf(acc[i][j] - rm); s += acc[i][j]; }
        red2[r * 16 + tx] = s;
    }
    __syncthreads();
    #pragma unroll
    for (int i = 0; i < 4; i++) {
        int r = ty * 4 + i;
        float rs = red2[r * 16];
        #pragma unroll
        for (int x = 1; x < 16; x++) rs += red2[r * 16 + x];
        inv_[i] = 1.0f / rs;
    }
    #pragma unroll
    for (int i = 0; i < 4; i++)
        #pragma unroll
        for (int j = 0; j < 12; j++)
            KT[(ty * 4 + i) * 196 + tx * 12 + j] = acc[i][j] * inv_[i];
    __syncthreads();

    float acc2[4][4];
    #pragma unroll
    for (int i = 0; i < 4; i++)
        #pragma unroll
        for (int j = 0; j < 4; j++) acc2[i][j] = 0.0f;
    for (int k = 0; k < 192; k++) {
        float4 b4 = *(const float4*)&Vs[k * 68 + tx * 4];
        #pragma unroll
        for (int i = 0; i < 4; i++) {
            float a = KT[(ty * 4 + i) * 196 + k];
            acc2[i][0] += a * b4.x; acc2[i][1] += a * b4.y;
            acc2[i][2] += a * b4.z; acc2[i][3] += a * b4.w;
        }
    }
    __syncthreads();
    #pragma unroll
    for (int i = 0; i < 4; i++)
        #pragma unroll
        for (int j = 0; j < 4; j++)
            QT[(ty * 4 + i) * 68 + tx * 4 + j] = acc2[i][j];
    for (int idx = t; idx < 4096; idx += 256) {
        int k = idx >> 6, n = idx & 63;
        Vs[k * 68 + n] = Wo[idx];
    }
    __syncthreads();

    float acc3[4][4];
    #pragma unroll
    for (int i = 0; i < 4; i++)
        #pragma unroll
        for (int j = 0; j < 4; j++) acc3[i][j] = 0.0f;
    for (int k = 0; k < 64; k++) {
        float4 b4 = *(const float4*)&Vs[k * 68 + tx * 4];
        #pragma unroll
        for (int i = 0; i < 4; i++) {
            float a = QT[(ty * 4 + i) * 68 + k];
            acc3[i][0] += a * b4.x; acc3[i][1] += a * b4.y;
            acc3[i][2] += a * b4.z; acc3[i][3] += a * b4.w;
        }
    }
    #pragma unroll
    for (int i = 0; i < 4; i++) {
        int tok = b * NP_ + row0 + ty * 4 + i;
        #pragma unroll
        for (int j = 0; j < 4; j++) {
            int n = tx * 4 + j;
            float v = acc3[i][j] + F[(size_t)tok * 64 + n];
            v = v * (scl[b * 64 + n] + 1.0f) + shf[b * 64 + n];
            F2[(size_t)tok * 64 + n] = v;
        }
    }
}

// ---------------- fused tail ----------------
#define TAIL_SMEM_FLOATS 13824
__global__ void __launch_bounds__(256, 1) tail_fused_kernel(
    const float* __restrict__ F2,
    const float* __restrict__ Wc1, const float* __restrict__ bc1,
    const float* __restrict__ Wc2, const float* __restrict__ bc2,
    const float* __restrict__ Wcls, const float* __restrict__ bcls,
    const float* __restrict__ Wr1, const float* __restrict__ br1,
    const float* __restrict__ Wr2, const float* __restrict__ br2,
    const float* __restrict__ Wreg, const float* __restrict__ breg,
    float* __restrict__ anchor, float* __restrict__ sxs, float* __restrict__ out)
{
    extern __shared__ float sm[];
    float* X  = sm;           // [32][68]
    float* T1 = sm + 2176;
    float* T2 = sm + 4352;
    float* Wb = sm + 6528;
    float* RG = sm + 11392;

    int row0 = blockIdx.x * 32;
    int t = threadIdx.x;
    int tx = t & 15, ty = t >> 4;

    for (int idx = t; idx < 2048; idx += 256) {
        int r = idx >> 6, n = idx & 63;
        X[r * 68 + n] = F2[(size_t)(row0 + r) * 64 + n];
    }
    for (int idx = t; idx < 4096; idx += 256)
        Wb[(idx >> 6) * 68 + (idx & 63)] = Wc1[idx];
    __syncthreads();

#define MM64(IN, OUT, BIAS)                                                    \
    {                                                                          \
        float a0, a1; float ac[2][4];                                          \
        ac[0][0]=ac[0][1]=ac[0][2]=ac[0][3]=0.0f;                              \
        ac[1][0]=ac[1][1]=ac[1][2]=ac[1][3]=0.0f;                              \
        for (int k = 0; k < 64; k++) {                                         \
            float4 b4 = *(const float4*)&Wb[k * 68 + tx * 4];                  \
            a0 = IN[(ty * 2 + 0) * 68 + k];                                    \
            a1 = IN[(ty * 2 + 1) * 68 + k];                                    \
            ac[0][0]+=a0*b4.x; ac[0][1]+=a0*b4.y; ac[0][2]+=a0*b4.z; ac[0][3]+=a0*b4.w; \
            ac[1][0]+=a1*b4.x; ac[1][1]+=a1*b4.y; ac[1][2]+=a1*b4.z; ac[1][3]+=a1*b4.w; \
        }                                                                      \
        for (int i = 0; i < 2; i++)                                            \
            for (int j = 0; j < 4; j++) {                                      \
                int n = tx * 4 + j;                                            \
                OUT[(ty * 2 + i) * 68 + n] = fmaxf(ac[i][j] + BIAS[n], 0.0f);  \
            }                                                                  \
    }

    MM64(X, T1, bc1);
    __syncthreads();
    for (int idx = t; idx < 4096; idx += 256)
        Wb[(idx >> 6) * 68 + (idx & 63)] = Wc2[idx];
    __syncthreads();
    MM64(T1, T2, bc2);
    __syncthreads();

    if (t < 64) {
        int r = t >> 1, c = t & 1;
        float s = bcls[c];
        #pragma unroll 8
        for (int k = 0; k < 64; k++) s += T2[r * 68 + k] * Wcls[k * 2 + c];
        out[(size_t)(row0 + r) * OUTW_ + c] = s;
    }
    for (int idx = t; idx < 4096; idx += 256)
        Wb[(idx >> 6) * 68 + (idx & 63)] = Wr1[idx];
    __syncthreads();
    MM64(X, T1, br1);
    __syncthreads();
    for (int idx = t; idx < 4096; idx += 256)
        Wb[(idx >> 6) * 68 + (idx & 63)] = Wr2[idx];
    __syncthreads();
    MM64(T1, T2, br2);
    __syncthreads();
    for (int idx = t; idx < 64 * 76; idx += 256) Wb[idx] = Wreg[idx];
    __syncthreads();
    for (int idx = t; idx < 32 * 76; idx += 256) {
        int r = idx / 76, n = idx - r * 76;
        float s = breg[n];
        #pragma unroll 8
        for (int k = 0; k < 64; k++) s += T2[r * 68 + k] * Wb[k * 76 + n];
        RG[idx] = s;
    }
    __syncthreads();

    if (t < 32) {
        int bp = row0 + t;
        const float* rg = &RG[t * 76];
        float sy = anchor[bp * 3 + 0] + rg[0];
        float sx = anchor[bp * 3 + 1] + rg[1];
        float th = anchor[bp * 3 + 2] + rg[2];
        anchor[bp * 3 + 0] = sy;
        anchor[bp * 3 + 1] = sx;
        anchor[bp * 3 + 2] = th;
        float tan_t = tanf(th * PI_F);
        float ts = (fabsf(tan_t) < 0.001f) ? 0.001f : tan_t;
        float coef = 0.4f / ts;
        float* o = out + (size_t)bp * OUTW_;
        o[2] = sy; o[3] = sx; o[4] = th;
        o[5] = rg[3];
        #pragma unroll 8
        for (int r = 0; r < NR_; r++) {
            float xr = sx + ((float)r * (1.0f / 71.0f) - sy) * coef;
            o[6 + r] = xr + rg[4 + r];
        }
        #pragma unroll
        for (int s = 0; s < NS_; s++) {
            int idx = SIDX(35 - s);
            sxs[bp * NS_ + s] = sx + ((float)idx * (1.0f / 71.0f) - sy) * coef;
        }
    }
#undef MM64
}

// ---------------- host ----------------
extern "C" void kernel_launch(void* const* d_in, const int* in_sizes, int n_in,
                              void* d_out, int out_size)
{
    const float *feat0 = nullptr, *feat1 = nullptr, *feat2 = nullptr, *inputs = nullptr;
    const int* tarr = nullptr;
    const float *W_t1 = nullptr, *b_t1 = nullptr, *W_t2 = nullptr, *b_t2 = nullptr;
    const float *W_st = nullptr, *b_st = nullptr, *W_tc = nullptr, *b_tc = nullptr;
    const float *W_fc = nullptr, *b_fc = nullptr;
    const float *W_q = nullptr, *W_k = nullptr, *W_v = nullptr, *W_o = nullptr;
    const float *W_c1 = nullptr, *b_c1 = nullptr, *W_c2 = nullptr, *b_c2 = nullptr;
    const float *W_r1 = nullptr, *b_r1 = nullptr, *W_r2 = nullptr, *b_r2 = nullptr;
    const float *W_cls = nullptr, *b_cls = nullptr, *W_reg = nullptr, *b_reg = nullptr;

    int idx16384 = 0, idx4096 = 0, idx256 = 0, idx64 = 0;
    int idxWst = -1;
    int idx128_pos[2] = {-1, -1}; int n128 = 0;
    const float* p4096[8] = {0};
    const float* p64[6] = {0};

    for (int i = 0; i < n_in; i++) {
        const float* p = (const float*)d_in[i];
        switch (in_sizes[i]) {
            case 8192000: feat0 = p; break;
            case 2048000: feat1 = p; break;
            case 512000:  feat2 = p; break;
            case 18432:   inputs = p; break;
            case 32:      tarr = (const int*)d_in[i]; break;
            case 65536:   W_t2 = p; break;
            case 32768:   W_st = p; idxWst = i; break;
            case 147456:  W_fc = p; break;
            case 4864:    W_reg = p; break;
            case 2:       b_cls = p; break;
            case 76:      b_reg = p; break;
            case 16384:   if (idx16384++ == 0) W_t1 = p; else W_tc = p; break;
            case 4096:    if (idx4096 < 8) p4096[idx4096++] = p; break;
            case 256:     if (idx256++ == 0) b_t1 = p; else b_t2 = p; break;
            case 64:      if (idx64 < 6) p64[idx64++] = p; break;
            case 128:     if (n128 < 2) idx128_pos[n128++] = i; break;
            default: break;
        }
    }
    W_q = p4096[0]; W_k = p4096[1]; W_v = p4096[2]; W_o = p4096[3];
    W_c1 = p4096[4]; W_c2 = p4096[5]; W_r1 = p4096[6]; W_r2 = p4096[7];
    b_tc = p64[0]; b_fc = p64[1]; b_c1 = p64[2]; b_c2 = p64[3]; b_r1 = p64[4]; b_r2 = p64[5];
    if (n128 == 2) {
        if (idx128_pos[0] == idxWst + 1) {
            b_st  = (const float*)d_in[idx128_pos[0]];
            W_cls = (const float*)d_in[idx128_pos[1]];
        } else if (idx128_pos[1] == idxWst + 1) {
            b_st  = (const float*)d_in[idx128_pos[1]];
            W_cls = (const float*)d_in[idx128_pos[0]];
        } else {
            W_cls = (const float*)d_in[idx128_pos[0]];
            b_st  = (const float*)d_in[idx128_pos[1]];
        }
    }

    static int attr_done = 0;
    static cudaStream_t s_side = nullptr;
    static cudaEvent_t ev_fork = nullptr, ev_join = nullptr;
    if (!attr_done) {
        cudaFuncSetAttribute(attn_fused_kernel, cudaFuncAttributeMaxDynamicSharedMemorySize,
                             ATT_SMEM_FLOATS * 4);
        cudaFuncSetAttribute(tail_fused_kernel, cudaFuncAttributeMaxDynamicSharedMemorySize,
                             TAIL_SMEM_FLOATS * 4);
        cudaFuncSetAttribute(qkvF_kernel, cudaFuncAttributeMaxDynamicSharedMemorySize,
                             QKVF_SMEM_FLOATS * 4);
        cudaStreamCreateWithFlags(&s_side, cudaStreamNonBlocking);
        cudaEventCreateWithFlags(&ev_fork, cudaEventDisableTiming);
        cudaEventCreateWithFlags(&ev_join, cudaEventDisableTiming);
        attr_done = 1;
    }

    float* S;
    cudaGetSymbolAddress((void**)&S, g_scratch);
    float* f0T = S + O_F0T;  float* f1T = S + O_F1T;  float* f2T = S + O_F2T;
    __nv_bfloat16* gAhi = (__nv_bfloat16*)(S + O_AHI);
    __nv_bfloat16* gAlo = (__nv_bfloat16*)(S + O_ALO);
    __nv_bfloat16* gBhi = (__nv_bfloat16*)(S + O_BHI);
    __nv_bfloat16* gBlo = (__nv_bfloat16*)(S + O_BLO);
    float* Wqkv = S + O_WQKV;
    float* gF = S + O_F; float* gF2 = S + O_F2; float* gQKV = S + O_QKV;
    float* gCP = S + O_CPART;
    float* gANCH = S + O_ANCH; float* gSXS = S + O_SXS;
    float* gTT = S + O_TT; float* gSCL = S + O_SCALE; float* gSHF = S + O_SHIFT;
    float* outP = (float*)d_out;

    const float* feats[3] = { f2T, f1T, f0T };
    const int Hs[3] = { 10, 20, 40 };
    const int Ws_[3] = { 25, 50, 100 };
    int gsBlocks = (M_ * NS_) / (32 * 8);   // 864, exact

    // Fork: f0+f1 transposes overlap with iteration 0 on a side stream.
    cudaEventRecord(ev_fork, 0);
    cudaStreamWaitEvent(s_side, ev_fork, 0);
    transpose_f01_kernel<<<dim3(157, 2, B_), dim3(32, 8), 0, s_side>>>(feat0, f0T, feat1, f1T);
    cudaEventRecord(ev_join, s_side);

    setup_misc_kernel<<<680, 256>>>(W_fc, gBhi, gBlo, W_q, W_k, W_v, Wqkv,
                                    inputs, gANCH, gSXS,
                                    tarr, W_t1, b_t1, W_t2, b_t2, W_st, b_st,
                                    W_tc, b_tc, gTT, gSCL, gSHF);
    transpose_f2_kernel<<<dim3(8, 2, B_), dim3(32, 8)>>>(feat2, f2T);

    for (int it = 0; it < 3; it++) {
        if (it == 1) cudaStreamWaitEvent(0, ev_join, 0);   // f0T/f1T ready before use
        gridsample_kernel<<<gsBlocks, 256>>>(feats[it], Hs[it], Ws_[it], gSXS, gAhi, gAlo);
        fc_mma_kernel<<<dim3(48, NSPLIT), 128>>>(gAhi, gAlo, gBhi, gBlo, gCP);
        qkvF_kernel<<<M_ / 64, 256, QKVF_SMEM_FLOATS * 4>>>(gCP, b_fc, gTT, Wqkv, gF, gQKV);
        attn_fused_kernel<<<B_ * 3, 256, ATT_SMEM_FLOATS * 4>>>(gQKV, W_o, gF, gSCL, gSHF, gF2);
        tail_fused_kernel<<<M_ / 32, 256, TAIL_SMEM_FLOATS * 4>>>(
            gF2, W_c1, b_c1, W_c2, b_c2, W_cls, b_cls, W_r1, b_r1, W_r2, b_r2,
            W_reg, b_reg, gANCH, gSXS, outP);
    }
    (void)out_size; (void)n_in;
}